// round 2
// baseline (speedup 1.0000x reference)
#include <cuda_runtime.h>
#include <math.h>

typedef unsigned long long ull;

#define B_   64
#define L_   49
#define ENC_ 2048
#define TMX  59
#define V_   10000

#define BM 64
#define BN 128
#define BK 32

// ---------------- scratch (device globals; no allocation allowed) ----------------
__device__ float g_mean[B_ * ENC_];                 // 64x2048
__device__ float g_hc[B_ * 1024];                   // [b][0:512]=h, [512:1024]=c
__device__ float g_hcslab[16 * B_ * 1024];          // h0/c0 split-K slabs
__device__ float g_encproj[3136 * 512];             // (B*L, A)
__device__ float g_emb[TMX * B_ * 512];             // [t][b][512]
__device__ float g_hp[4 * B_ * 2560];               // h@[dec_att|actv] slabs
__device__ float g_gattv[B_ * 2048];                // gate * att_vec
__device__ float g_gs[12 * B_ * 2048];              // gates GEMM slabs
__device__ float g_hall[TMX * B_ * 512];            // h_new per step (for deferred fc)

// ---------------- f32x2 helpers ----------------
__device__ __forceinline__ ull pk2(float lo, float hi) {
    ull r; asm("mov.b64 %0, {%1,%2};" : "=l"(r) : "f"(lo), "f"(hi)); return r;
}
__device__ __forceinline__ void fma2(ull& d, ull a, ull b) {
    asm("fma.rn.f32x2 %0, %1, %2, %0;" : "+l"(d) : "l"(a), "l"(b));
}
__device__ __forceinline__ float2 upk2(ull v) {
    float2 f; asm("mov.b64 {%0,%1}, %2;" : "=f"(f.x), "=f"(f.y) : "l"(v)); return f;
}

// =====================================================================
// Generic tiled GEMM: C[M,N] (+)= A[M,K] @ W[K,N]
//  - A side: up to 3 row-segments (k-ranges) with independent ptr/lda
//  - W side: either a K-split (k >= wSplitK -> Wb) or an N-split
//    (pcol >= wSplitN -> Wb). Only one active per launch.
//  - gather: output/W columns remapped pc = (j>>5)*512 + bx*32 + (j&31)
//    (used to co-locate the 4 LSTM gate slices per block).
//  - blockIdx.z = split-K slab index, Kslab elems each, slab output.
//  - epi 0 + bias!=0 (gridDim.z==1): direct write acc+bias
//    epi 0 + bias==0: slab write
//    epi 2: fc epilogue (bias + active mask + scatter to (b,t,V) layout)
// =====================================================================
__global__ void __launch_bounds__(256, 2) gemm_f32(
    const float* __restrict__ A0, int ka0, int lda0,
    const float* __restrict__ A1, int ka1, int lda1,
    const float* __restrict__ A2, int lda2,
    const float* __restrict__ Wa, const float* __restrict__ Wb,
    int wSplitK, int wSplitN, int ldwa, int ldwb,
    int Ntot, int Kslab, int gather,
    float* __restrict__ Cslab, long long slabStride,
    const float* __restrict__ bias,
    int epi, const int* __restrict__ lens, float* __restrict__ outPred)
{
    __shared__ float As[BM][36];      // padded: 36*4=144 bytes/row (16B aligned)
    __shared__ float Ws[BK][BN];

    const int tid  = threadIdx.x;
    const int trow = tid >> 4;        // 16 row groups x 4 rows
    const int tcol = tid & 15;        // 16 col groups x 8 cols
    const int row0 = blockIdx.y * BM;
    const int bx   = blockIdx.x;
    const int z    = blockIdx.z;
    const int kbase0 = z * Kslab;

    ull acc[4][4];
#pragma unroll
    for (int r = 0; r < 4; r++)
#pragma unroll
        for (int c = 0; c < 4; c++) acc[r][c] = 0ull;

    const int nChunks = Kslab / BK;
    for (int ch = 0; ch < nChunks; ch++) {
        const int kb = kbase0 + ch * BK;

        // ---- load A tile (64x32) as float4, segment-resolved ----
#pragma unroll
        for (int i = 0; i < 2; i++) {
            int q  = tid * 2 + i;          // float4 index
            int m  = q >> 3;
            int kk = (q & 7) * 4;
            int k  = kb + kk;
            const float* Ap; int krel, lda;
            if (k < ka0)            { Ap = A0; krel = k;             lda = lda0; }
            else if (k < ka0 + ka1) { Ap = A1; krel = k - ka0;       lda = lda1; }
            else                    { Ap = A2; krel = k - ka0 - ka1; lda = lda2; }
            float4 v = *(const float4*)&Ap[(size_t)(row0 + m) * lda + krel];
            *(float4*)&As[m][kk] = v;
        }

        // ---- load W tile (32x128) as float4, split/gather/bounds-resolved ----
        {
            int jq  = tid & 31;            // float4 column
            int kkq = tid >> 5;
#pragma unroll
            for (int i = 0; i < 4; i++) {
                int kk = kkq + i * 8;
                int k  = kb + kk;
                int j  = jq * 4;
                int pc = gather ? ((j >> 5) * 512 + bx * 32 + (j & 31))
                                : (bx * BN + j);
                const float* Wp = Wa; int kr = k, cc = pc, ldw = ldwa;
                if (k >= wSplitK)       { Wp = Wb; kr = k - wSplitK;  ldw = ldwb; }
                else if (pc >= wSplitN) { Wp = Wb; cc = pc - wSplitN; ldw = ldwb; }
                float4 v;
                if (pc + 3 < Ntot) {
                    v = *(const float4*)&Wp[(size_t)kr * ldw + cc];
                } else {
                    v.x = (pc + 0 < Ntot) ? Wp[(size_t)kr * ldw + cc + 0] : 0.f;
                    v.y = (pc + 1 < Ntot) ? Wp[(size_t)kr * ldw + cc + 1] : 0.f;
                    v.z = (pc + 2 < Ntot) ? Wp[(size_t)kr * ldw + cc + 2] : 0.f;
                    v.w = 0.f;
                }
                *(float4*)&Ws[kk][j] = v;
            }
        }
        __syncthreads();

        // ---- f32x2 inner product ----
#pragma unroll
        for (int kk = 0; kk < BK; kk++) {
            const ull* wb = (const ull*)&Ws[kk][tcol * 8];
            ull b0 = wb[0], b1 = wb[1], b2 = wb[2], b3 = wb[3];
#pragma unroll
            for (int r = 0; r < 4; r++) {
                float a = As[trow * 4 + r][kk];
                ull a2 = pk2(a, a);
                fma2(acc[r][0], a2, b0);
                fma2(acc[r][1], a2, b1);
                fma2(acc[r][2], a2, b2);
                fma2(acc[r][3], a2, b3);
            }
        }
        __syncthreads();
    }

    // ---- epilogue ----
#pragma unroll
    for (int r = 0; r < 4; r++) {
        int mloc = row0 + trow * 4 + r;
#pragma unroll
        for (int c = 0; c < 4; c++) {
            float2 f = upk2(acc[r][c]);
            int j  = tcol * 8 + c * 2;
            int pc = gather ? ((j >> 5) * 512 + bx * 32 + (j & 31))
                            : (bx * BN + j);
            if (epi == 2) {
                int tt = mloc >> 6, bb = mloc & 63;
                bool act = tt < (lens[bb] - 1);
                size_t base = ((size_t)bb * TMX + tt) * (size_t)V_;
                if (pc + 1 < Ntot) {
                    float2 o;
                    o.x = act ? (f.x + bias[pc])     : 0.f;
                    o.y = act ? (f.y + bias[pc + 1]) : 0.f;
                    *(float2*)&outPred[base + pc] = o;
                } else if (pc < Ntot) {
                    outPred[base + pc] = act ? (f.x + bias[pc]) : 0.f;
                }
            } else if (bias) {
                float* o = Cslab + (size_t)mloc * Ntot;
                if (pc     < Ntot) o[pc]     = f.x + bias[pc];
                if (pc + 1 < Ntot) o[pc + 1] = f.y + bias[pc + 1];
            } else {
                float* o = Cslab + (size_t)z * slabStride + (size_t)mloc * Ntot;
                if (pc + 1 < Ntot) { o[pc] = f.x; o[pc + 1] = f.y; }
                else if (pc < Ntot) o[pc] = f.x;
            }
        }
    }
}

// ---------------- mean over L ----------------
__global__ void mean_kernel(const float* __restrict__ in) {
    int idx = blockIdx.x * 256 + threadIdx.x;   // over B*ENC
    if (idx >= B_ * ENC_) return;
    int b = idx >> 11, e = idx & 2047;
    float s = 0.f;
#pragma unroll 7
    for (int l = 0; l < L_; l++) s += in[((size_t)b * L_ + l) * ENC_ + e];
    g_mean[idx] = s * (1.0f / 49.0f);
}

// ---------------- h0/c0 slab reduce + bias ----------------
__global__ void hc_reduce(const float* __restrict__ hb, const float* __restrict__ cb) {
    int idx = blockIdx.x * 256 + threadIdx.x;   // 64*1024
    int n = idx & 1023;
    float s = (n < 512) ? hb[n] : cb[n - 512];
#pragma unroll
    for (int zz = 0; zz < 16; zz++) s += g_hcslab[zz * (B_ * 1024) + idx];
    g_hc[idx] = s;
}

// ---------------- embedding gather ----------------
__global__ void emb_gather(const float* __restrict__ embed_w, const int* __restrict__ captions) {
    int idx = blockIdx.x * 256 + threadIdx.x;   // TMX*B*512
    if (idx >= TMX * B_ * 512) return;
    int e = idx & 511;
    int tb = idx >> 9;
    int b = tb & 63, t = tb >> 6;
    int tok = captions[b * 60 + t];
    g_emb[idx] = embed_w[(size_t)tok * 512 + e];
}

// ---------------- fused attention: scores -> softmax -> att_vec -> gate ----------------
__global__ void __launch_bounds__(256) attn_kernel(
    const float* __restrict__ input,
    const float* __restrict__ dec_b,
    const float* __restrict__ att_w,
    const float* __restrict__ att_b,
    const float* __restrict__ actv_b,
    const int* __restrict__ lens,
    float* __restrict__ outProbs, int t)
{
    __shared__ float sd[512];
    __shared__ float sp[64];

    const int b = blockIdx.x;
    const int tid = threadIdx.x;

    // dproj = sum of 4 h-proj slabs + dec_att_b
    for (int i = tid; i < 512; i += 256) {
        float s = dec_b[i];
#pragma unroll
        for (int zz = 0; zz < 4; zz++) s += g_hp[zz * (B_ * 2560) + b * 2560 + i];
        sd[i] = s;
    }
    __syncthreads();

    const int w = tid >> 5, lane = tid & 31;
    // scores over L
    for (int l = w; l < L_; l += 8) {
        const float* ep = g_encproj + ((size_t)b * L_ + l) * 512;
        float s = 0.f;
        for (int a = lane; a < 512; a += 32) {
            float v = ep[a] + sd[a];
            v = fmaxf(v, 0.f);
            s = fmaf(v, att_w[a], s);
        }
#pragma unroll
        for (int o = 16; o; o >>= 1) s += __shfl_xor_sync(~0u, s, o);
        if (lane == 0) sp[l] = s + att_b[0];
    }
    __syncthreads();

    // softmax over L (warp 0)
    if (w == 0) {
        float v0 = (lane < L_) ? sp[lane] : -1e30f;
        float v1 = (lane + 32 < L_) ? sp[lane + 32] : -1e30f;
        float mx = fmaxf(v0, v1);
#pragma unroll
        for (int o = 16; o; o >>= 1) mx = fmaxf(mx, __shfl_xor_sync(~0u, mx, o));
        float e0 = (lane < L_) ? expf(v0 - mx) : 0.f;
        float e1 = (lane + 32 < L_) ? expf(v1 - mx) : 0.f;
        float sm = e0 + e1;
#pragma unroll
        for (int o = 16; o; o >>= 1) sm += __shfl_xor_sync(~0u, sm, o);
        float inv = 1.f / sm;
        if (lane < L_) sp[lane] = e0 * inv;
        if (lane + 32 < L_) sp[lane + 32] = e1 * inv;
    }
    __syncthreads();

    const bool act = t < (lens[b] - 1);
    if (tid < L_) outProbs[((size_t)b * TMX + t) * L_ + tid] = act ? sp[tid] : 0.f;

    // att_vec (weighted sum over L) then gate*att_vec
    const int e0 = tid * 8;
    float4 a0 = make_float4(0, 0, 0, 0), a1 = make_float4(0, 0, 0, 0);
    const float* ip = input + (size_t)b * L_ * ENC_ + e0;
    for (int l = 0; l < L_; l++) {
        float p = sp[l];
        float4 x0 = *(const float4*)(ip + (size_t)l * ENC_);
        float4 x1 = *(const float4*)(ip + (size_t)l * ENC_ + 4);
        a0.x = fmaf(p, x0.x, a0.x); a0.y = fmaf(p, x0.y, a0.y);
        a0.z = fmaf(p, x0.z, a0.z); a0.w = fmaf(p, x0.w, a0.w);
        a1.x = fmaf(p, x1.x, a1.x); a1.y = fmaf(p, x1.y, a1.y);
        a1.z = fmaf(p, x1.z, a1.z); a1.w = fmaf(p, x1.w, a1.w);
    }
    float res[8] = {a0.x, a0.y, a0.z, a0.w, a1.x, a1.y, a1.z, a1.w};
#pragma unroll
    for (int i = 0; i < 8; i++) {
        int e = e0 + i;
        float hp = actv_b[e];
#pragma unroll
        for (int zz = 0; zz < 4; zz++) hp += g_hp[zz * (B_ * 2560) + b * 2560 + 512 + e];
        float gate = 1.f / (1.f + expf(-hp));
        g_gattv[b * ENC_ + e] = gate * res[i];
    }
}

// ---------------- gates slab-reduce + LSTM pointwise + carry update ----------------
__global__ void lstm_kernel(const float* __restrict__ bih, const float* __restrict__ bhh,
                            const int* __restrict__ lens, int t)
{
    int idx = blockIdx.x * 256 + threadIdx.x;   // 64*512
    int b = idx >> 9, n = idx & 511;
    float gi = bih[n]        + bhh[n];
    float gf = bih[n + 512]  + bhh[n + 512];
    float gg = bih[n + 1024] + bhh[n + 1024];
    float go = bih[n + 1536] + bhh[n + 1536];
#pragma unroll
    for (int zz = 0; zz < 12; zz++) {
        const float* gs = g_gs + zz * (B_ * 2048) + b * 2048;
        gi += gs[n]; gf += gs[n + 512]; gg += gs[n + 1024]; go += gs[n + 1536];
    }
    float c  = g_hc[b * 1024 + 512 + n];
    float i_ = 1.f / (1.f + expf(-gi));
    float f_ = 1.f / (1.f + expf(-gf));
    float o_ = 1.f / (1.f + expf(-go));
    float cn = f_ * c + i_ * tanhf(gg);
    float hn = o_ * tanhf(cn);
    g_hall[((size_t)t * B_ + b) * 512 + n] = hn;
    if (t < (lens[b] - 1)) {
        g_hc[b * 1024 + n] = hn;
        g_hc[b * 1024 + 512 + n] = cn;
    }
}

// =====================================================================
extern "C" void kernel_launch(void* const* d_in, const int* in_sizes, int n_in,
                              void* d_out, int out_size)
{
    const float* input     = (const float*)d_in[0];
    const int*   captions  = (const int*)  d_in[1];
    const int*   lens      = (const int*)  d_in[2];
    const float* embed_w   = (const float*)d_in[3];
    const float* enc_att_w = (const float*)d_in[4];
    const float* enc_att_b = (const float*)d_in[5];
    const float* dec_att_w = (const float*)d_in[6];
    const float* dec_att_b = (const float*)d_in[7];
    const float* att_w     = (const float*)d_in[8];
    const float* att_b     = (const float*)d_in[9];
    const float* h_w       = (const float*)d_in[10];
    const float* h_b       = (const float*)d_in[11];
    const float* c_w       = (const float*)d_in[12];
    const float* c_b       = (const float*)d_in[13];
    const float* actv_w    = (const float*)d_in[14];
    const float* actv_b    = (const float*)d_in[15];
    const float* wih       = (const float*)d_in[16];
    const float* whh       = (const float*)d_in[17];
    const float* bih       = (const float*)d_in[18];
    const float* bhh       = (const float*)d_in[19];
    const float* fc_w      = (const float*)d_in[20];
    const float* fc_b      = (const float*)d_in[21];

    float* out      = (float*)d_out;
    float* outProbs = out + (size_t)B_ * TMX * V_;

    void* p;
    cudaGetSymbolAddress(&p, g_mean);    float* p_mean    = (float*)p;
    cudaGetSymbolAddress(&p, g_hc);      float* p_hc      = (float*)p;
    cudaGetSymbolAddress(&p, g_hcslab);  float* p_hcslab  = (float*)p;
    cudaGetSymbolAddress(&p, g_encproj); float* p_encproj = (float*)p;
    cudaGetSymbolAddress(&p, g_emb);     float* p_emb     = (float*)p;
    cudaGetSymbolAddress(&p, g_hp);      float* p_hp      = (float*)p;
    cudaGetSymbolAddress(&p, g_gattv);   float* p_gattv   = (float*)p;
    cudaGetSymbolAddress(&p, g_gs);      float* p_gs      = (float*)p;
    cudaGetSymbolAddress(&p, g_hall);    float* p_hall    = (float*)p;

    const int HUGE_K = 1 << 30;

    // 1) mean over L
    mean_kernel<<<(B_ * ENC_ + 255) / 256, 256>>>(input);

    // 2) h0/c0 = mean @ [h_w | c_w] + bias  (split-K 16 slabs of 128)
    gemm_f32<<<dim3(8, 1, 16), 256>>>(
        p_mean, HUGE_K, ENC_,  p_mean, 0, 0,  p_mean, 0,
        h_w, c_w, HUGE_K, 512, 512, 512,
        1024, 128, 0,
        p_hcslab, (long long)B_ * 1024, nullptr, 0, nullptr, nullptr);
    hc_reduce<<<(B_ * 1024) / 256, 256>>>(h_b, c_b);

    // 3) enc_proj = input @ enc_att_w + enc_att_b  (direct bias epilogue)
    gemm_f32<<<dim3(4, 49, 1), 256>>>(
        input, HUGE_K, ENC_,  input, 0, 0,  input, 0,
        enc_att_w, enc_att_w, HUGE_K, HUGE_K, 512, 512,
        512, 2048, 0,
        p_encproj, 0, enc_att_b, 0, nullptr, nullptr);

    // 4) embedding gather for all steps
    emb_gather<<<(TMX * B_ * 512 + 255) / 256, 256>>>(embed_w, captions);

    // 5) recurrence
    for (int t = 0; t < TMX; t++) {
        // hp = h @ [dec_att_w | actv_w]   (N=2560, split-K 4 slabs of 128)
        gemm_f32<<<dim3(20, 1, 4), 256>>>(
            p_hc, HUGE_K, 1024,  p_hc, 0, 0,  p_hc, 0,
            dec_att_w, actv_w, HUGE_K, 512, 512, 2048,
            2560, 128, 0,
            p_hp, (long long)B_ * 2560, nullptr, 0, nullptr, nullptr);

        // attention + softmax + att_vec + gate (also writes probs output)
        attn_kernel<<<B_, 256>>>(input, dec_att_b, att_w, att_b, actv_b,
                                 lens, outProbs, t);

        // gates = [emb_t | gattv | h] @ [wih ; whh]  (gathered cols, split-K 12x256)
        gemm_f32<<<dim3(16, 1, 12), 256>>>(
            p_emb + (size_t)t * B_ * 512, 512, 512,
            p_gattv, 2048, 2048,
            p_hc, 1024,
            wih, whh, 2560, HUGE_K, 2048, 2048,
            2048, 256, 1,
            p_gs, (long long)B_ * 2048, nullptr, 0, nullptr, nullptr);

        // slab reduce + LSTM pointwise + masked carry update + stash h_new
        lstm_kernel<<<(B_ * 512) / 256, 256>>>(bih, bhh, lens, t);
    }

    // 6) deferred fc: preds = mask(h_all @ fc_w + fc_b), scattered to (b,t,V)
    gemm_f32<<<dim3(79, 59, 1), 256>>>(
        p_hall, HUGE_K, 512,  p_hall, 0, 0,  p_hall, 0,
        fc_w, fc_w, HUGE_K, HUGE_K, V_, V_,
        V_, 512, 0,
        nullptr, 0, fc_b, 2, lens, out);
}

// round 3
// speedup vs baseline: 1.2929x; 1.2929x over previous
#include <cuda_runtime.h>
#include <math.h>

typedef unsigned long long ull;

#define B_   64
#define L_   49
#define ENC_ 2048
#define TMX  59
#define V_   10000
#define BK   16
#define BN   128

// ---------------- scratch ----------------
__device__ float g_mean[B_ * ENC_];
__device__ float g_hc[B_ * 1024];
__device__ float g_hcslab[16 * B_ * 1024];
__device__ float g_encslab[2 * 3136 * 512];
__device__ float g_encproj[3136 * 512];
__device__ float g_emb[TMX * B_ * 512];
__device__ float g_hp[4 * B_ * 2560];
__device__ float g_gattv[B_ * 2048];
__device__ float g_gs[8 * B_ * 2048];
__device__ float g_hall[B_ * TMX * 512];          // [b][t][512]

// ---------------- f32x2 helpers ----------------
__device__ __forceinline__ ull pk2(float lo, float hi) {
    ull r; asm("mov.b64 %0, {%1,%2};" : "=l"(r) : "f"(lo), "f"(hi)); return r;
}
__device__ __forceinline__ void fma2(ull& d, ull a, ull b) {
    asm("fma.rn.f32x2 %0, %1, %2, %0;" : "+l"(d) : "l"(a), "l"(b));
}
__device__ __forceinline__ float2 upk2(ull v) {
    float2 f; asm("mov.b64 {%0,%1}, %2;" : "=f"(f.x), "=f"(f.y) : "l"(v)); return f;
}

// =====================================================================
// Templated GEMM. TM = rows/thread (8 -> BM=128, 4 -> BM=64). BN=128.
// 256 threads: rg=tid>>4 (16 row groups), cg=tid&15 (16 col groups of 8).
// A pre-duplicated in smem as f32x2 pairs; double-buffered staging.
// =====================================================================
template<int TM>
__global__ void __launch_bounds__(256, 2) gemm_f32(
    const float* __restrict__ A0, int ka0, int lda0,
    const float* __restrict__ A1, int ka1, int lda1,
    const float* __restrict__ A2, int lda2,
    const float* __restrict__ Wa, const float* __restrict__ Wb,
    int wSplitK, int wSplitN, int ldwa, int ldwb,
    int Mtot, int Ntot, int Kslab, int gather,
    float* __restrict__ Cslab, long long slabStride,
    const float* __restrict__ bias, int epi,
    const int* __restrict__ lens, float* __restrict__ outPred)
{
    constexpr int BM = TM * 16;
    constexpr int NA = BM / 64;

    __shared__ ull   Asd[2][BK][BM];
    __shared__ uint4 Ws4[2][BK][32];

    const int tid  = threadIdx.x;
    const int rg   = tid >> 4;
    const int cg   = tid & 15;
    const int row0 = blockIdx.y * BM;
    const int bx   = blockIdx.x;
    const int z    = blockIdx.z;
    const int kbase = z * Kslab;
    const int nCh   = Kslab / BK;

    if (epi == 2) {
        int* sact = (int*)&Asd[0][0][0];
        if (tid == 0) sact[0] = 0;
        __syncthreads();
        if (tid < BM) {
            int mloc = row0 + tid;
            if (mloc < Mtot) {
                int b = mloc / TMX, t = mloc - b * TMX;
                if (t < lens[b] - 1) sact[0] = 1;
            }
        }
        __syncthreads();
        int actv = sact[0];
        __syncthreads();
        if (!actv) {
#pragma unroll
            for (int r = 0; r < TM; r++) {
                int mloc = row0 + rg * TM + r;
                if (mloc >= Mtot) continue;
                size_t base = (size_t)mloc * V_;
                int j0 = bx * BN + cg * 8;
#pragma unroll
                for (int c = 0; c < 4; c++) {
                    int pc = j0 + 2 * c;
                    if (pc + 1 < Ntot) *(float2*)&outPred[base + pc] = make_float2(0.f, 0.f);
                    else if (pc < Ntot) outPred[base + pc] = 0.f;
                }
            }
            return;
        }
    }

    float4 av[NA], wv[2];

    auto loadA = [&](int kb) {
#pragma unroll
        for (int i = 0; i < NA; i++) {
            int id  = tid + i * 256;
            int m   = id >> 2;
            int kk4 = (id & 3) * 4;
            int k   = kb + kk4;
            int mg  = row0 + m;
            float4 v = make_float4(0.f, 0.f, 0.f, 0.f);
            if (mg < Mtot) {
                const float* Ap; int kr, lda;
                if (k < ka0)            { Ap = A0; kr = k;             lda = lda0; }
                else if (k < ka0 + ka1) { Ap = A1; kr = k - ka0;       lda = lda1; }
                else                    { Ap = A2; kr = k - ka0 - ka1; lda = lda2; }
                v = *(const float4*)&Ap[(size_t)mg * lda + kr];
            }
            av[i] = v;
        }
    };
    auto loadW = [&](int kb) {
#pragma unroll
        for (int i = 0; i < 2; i++) {
            int q  = tid & 31;
            int kk = (tid >> 5) + i * 8;
            int k  = kb + kk;
            int j  = q * 4;
            int pc = gather ? ((j >> 5) * 512 + bx * 32 + (j & 31)) : (bx * BN + j);
            const float* Wp = Wa; int kr = k, cc = pc, ldw = ldwa;
            if (k >= wSplitK)       { Wp = Wb; kr = k - wSplitK;  ldw = ldwb; }
            else if (pc >= wSplitN) { Wp = Wb; cc = pc - wSplitN; ldw = ldwb; }
            float4 v;
            if (pc + 3 < Ntot) {
                v = *(const float4*)&Wp[(size_t)kr * ldw + cc];
            } else {
                v.x = (pc     < Ntot) ? Wp[(size_t)kr * ldw + cc]     : 0.f;
                v.y = (pc + 1 < Ntot) ? Wp[(size_t)kr * ldw + cc + 1] : 0.f;
                v.z = (pc + 2 < Ntot) ? Wp[(size_t)kr * ldw + cc + 2] : 0.f;
                v.w = 0.f;
            }
            wv[i] = v;
        }
    };
    auto stage = [&](int buf) {
#pragma unroll
        for (int i = 0; i < NA; i++) {
            int id  = tid + i * 256;
            int m   = id >> 2;
            int kk4 = (id & 3) * 4;
            Asd[buf][kk4 + 0][m] = pk2(av[i].x, av[i].x);
            Asd[buf][kk4 + 1][m] = pk2(av[i].y, av[i].y);
            Asd[buf][kk4 + 2][m] = pk2(av[i].z, av[i].z);
            Asd[buf][kk4 + 3][m] = pk2(av[i].w, av[i].w);
        }
#pragma unroll
        for (int i = 0; i < 2; i++) {
            int q    = tid & 31;
            int kk   = (tid >> 5) + i * 8;
            int slot = (q & 1) ? (16 + (q >> 1)) : (q >> 1);
            Ws4[buf][kk][slot] = *(uint4*)&wv[i];
        }
    };

    ull acc[TM][4];
#pragma unroll
    for (int r = 0; r < TM; r++)
#pragma unroll
        for (int c = 0; c < 4; c++) acc[r][c] = 0ull;

    loadA(kbase); loadW(kbase); stage(0);
    __syncthreads();

    for (int ch = 0; ch < nCh; ch++) {
        const int cb = ch & 1;
        const bool more = (ch + 1) < nCh;
        if (more) { loadA(kbase + (ch + 1) * BK); loadW(kbase + (ch + 1) * BK); }

#pragma unroll
        for (int kk = 0; kk < BK; kk++) {
            uint4 wa_ = Ws4[cb][kk][cg];
            uint4 wb_ = Ws4[cb][kk][16 + cg];
            ull b0 = *(ull*)&wa_.x, b1 = *(ull*)&wa_.z;
            ull b2 = *(ull*)&wb_.x, b3 = *(ull*)&wb_.z;
            const ulonglong2* ap = (const ulonglong2*)&Asd[cb][kk][rg * TM];
#pragma unroll
            for (int pr = 0; pr < TM / 2; pr++) {
                ulonglong2 a2 = ap[pr];
                fma2(acc[2 * pr][0], a2.x, b0);
                fma2(acc[2 * pr][1], a2.x, b1);
                fma2(acc[2 * pr][2], a2.x, b2);
                fma2(acc[2 * pr][3], a2.x, b3);
                fma2(acc[2 * pr + 1][0], a2.y, b0);
                fma2(acc[2 * pr + 1][1], a2.y, b1);
                fma2(acc[2 * pr + 1][2], a2.y, b2);
                fma2(acc[2 * pr + 1][3], a2.y, b3);
            }
        }
        if (more) stage(cb ^ 1);
        __syncthreads();
    }

#pragma unroll
    for (int r = 0; r < TM; r++) {
        int mloc = row0 + rg * TM + r;
        if (mloc >= Mtot) continue;
#pragma unroll
        for (int c = 0; c < 4; c++) {
            float2 f = upk2(acc[r][c]);
            int j  = cg * 8 + 2 * c;
            int pc = gather ? ((j >> 5) * 512 + bx * 32 + (j & 31)) : (bx * BN + j);
            if (epi == 2) {
                int b = mloc / TMX, t = mloc - b * TMX;
                bool act = t < (lens[b] - 1);
                size_t base = (size_t)mloc * V_;
                if (pc + 1 < Ntot) {
                    float2 o;
                    o.x = act ? (f.x + bias[pc])     : 0.f;
                    o.y = act ? (f.y + bias[pc + 1]) : 0.f;
                    *(float2*)&outPred[base + pc] = o;
                } else if (pc < Ntot) {
                    outPred[base + pc] = act ? (f.x + bias[pc]) : 0.f;
                }
            } else if (bias) {
                float* o = Cslab + (size_t)mloc * Ntot;
                if (pc + 1 < Ntot) { o[pc] = f.x + bias[pc]; o[pc + 1] = f.y + bias[pc + 1]; }
                else if (pc < Ntot) o[pc] = f.x + bias[pc];
            } else {
                float* o = Cslab + (size_t)z * slabStride + (size_t)mloc * Ntot;
                if (pc + 1 < Ntot) *(float2*)&o[pc] = f;
                else if (pc < Ntot) o[pc] = f.x;
            }
        }
    }
}

// ---------------- small kernels ----------------
__global__ void mean_kernel(const float* __restrict__ in) {
    int idx = blockIdx.x * 256 + threadIdx.x;
    if (idx >= B_ * ENC_) return;
    int b = idx >> 11, e = idx & 2047;
    float s = 0.f;
#pragma unroll 7
    for (int l = 0; l < L_; l++) s += in[((size_t)b * L_ + l) * ENC_ + e];
    g_mean[idx] = s * (1.0f / 49.0f);
}

__global__ void hc_reduce(const float* __restrict__ hb, const float* __restrict__ cb) {
    int idx = blockIdx.x * 256 + threadIdx.x;
    int n = idx & 1023;
    float s = (n < 512) ? hb[n] : cb[n - 512];
#pragma unroll
    for (int zz = 0; zz < 16; zz++) s += g_hcslab[zz * (B_ * 1024) + idx];
    g_hc[idx] = s;
}

__global__ void enc_reduce(const float* __restrict__ eb) {
    int idx = blockIdx.x * 256 + threadIdx.x;
    g_encproj[idx] = g_encslab[idx] + g_encslab[3136 * 512 + idx] + eb[idx & 511];
}

__global__ void emb_gather(const float* __restrict__ embed_w, const int* __restrict__ captions) {
    int idx = blockIdx.x * 256 + threadIdx.x;
    if (idx >= TMX * B_ * 512) return;
    int e = idx & 511;
    int tb = idx >> 9;
    int b = tb & 63, t = tb >> 6;
    int tok = captions[b * 60 + t];
    g_emb[idx] = embed_w[(size_t)tok * 512 + e];
}

__global__ void __launch_bounds__(256) attn_kernel(
    const float* __restrict__ input,
    const float* __restrict__ dec_b,
    const float* __restrict__ att_w,
    const float* __restrict__ att_b,
    const float* __restrict__ actv_b,
    const int* __restrict__ lens,
    float* __restrict__ outProbs, int t)
{
    __shared__ float sd[512];
    __shared__ float sp[64];

    const int b = blockIdx.x;
    const int tid = threadIdx.x;

    for (int i = tid; i < 512; i += 256) {
        float s = dec_b[i];
#pragma unroll
        for (int zz = 0; zz < 4; zz++) s += g_hp[zz * (B_ * 2560) + b * 2560 + i];
        sd[i] = s;
    }
    __syncthreads();

    const int w = tid >> 5, lane = tid & 31;
    for (int l = w; l < L_; l += 8) {
        const float* ep = g_encproj + ((size_t)b * L_ + l) * 512;
        float s = 0.f;
        for (int a = lane; a < 512; a += 32) {
            float v = ep[a] + sd[a];
            v = fmaxf(v, 0.f);
            s = fmaf(v, att_w[a], s);
        }
#pragma unroll
        for (int o = 16; o; o >>= 1) s += __shfl_xor_sync(~0u, s, o);
        if (lane == 0) sp[l] = s + att_b[0];
    }
    __syncthreads();

    if (w == 0) {
        float v0 = (lane < L_) ? sp[lane] : -1e30f;
        float v1 = (lane + 32 < L_) ? sp[lane + 32] : -1e30f;
        float mx = fmaxf(v0, v1);
#pragma unroll
        for (int o = 16; o; o >>= 1) mx = fmaxf(mx, __shfl_xor_sync(~0u, mx, o));
        float e0 = (lane < L_) ? expf(v0 - mx) : 0.f;
        float e1 = (lane + 32 < L_) ? expf(v1 - mx) : 0.f;
        float sm = e0 + e1;
#pragma unroll
        for (int o = 16; o; o >>= 1) sm += __shfl_xor_sync(~0u, sm, o);
        float inv = 1.f / sm;
        if (lane < L_) sp[lane] = e0 * inv;
        if (lane + 32 < L_) sp[lane + 32] = e1 * inv;
    }
    __syncthreads();

    const bool act = t < (lens[b] - 1);
    if (tid < L_) outProbs[((size_t)b * TMX + t) * L_ + tid] = act ? sp[tid] : 0.f;

    const int e0i = tid * 8;
    float4 a0 = make_float4(0, 0, 0, 0), a1 = make_float4(0, 0, 0, 0);
    const float* ip = input + (size_t)b * L_ * ENC_ + e0i;
    for (int l = 0; l < L_; l++) {
        float p = sp[l];
        float4 x0 = *(const float4*)(ip + (size_t)l * ENC_);
        float4 x1 = *(const float4*)(ip + (size_t)l * ENC_ + 4);
        a0.x = fmaf(p, x0.x, a0.x); a0.y = fmaf(p, x0.y, a0.y);
        a0.z = fmaf(p, x0.z, a0.z); a0.w = fmaf(p, x0.w, a0.w);
        a1.x = fmaf(p, x1.x, a1.x); a1.y = fmaf(p, x1.y, a1.y);
        a1.z = fmaf(p, x1.z, a1.z); a1.w = fmaf(p, x1.w, a1.w);
    }
    float res[8] = {a0.x, a0.y, a0.z, a0.w, a1.x, a1.y, a1.z, a1.w};
#pragma unroll
    for (int i = 0; i < 8; i++) {
        int e = e0i + i;
        float hp = actv_b[e];
#pragma unroll
        for (int zz = 0; zz < 4; zz++) hp += g_hp[zz * (B_ * 2560) + b * 2560 + 512 + e];
        float gate = 1.f / (1.f + expf(-hp));
        g_gattv[b * ENC_ + e] = gate * res[i];
    }
}

__global__ void lstm_kernel(const float* __restrict__ bih, const float* __restrict__ bhh,
                            const int* __restrict__ lens, int t)
{
    int idx = blockIdx.x * 256 + threadIdx.x;
    int b = idx >> 9, n = idx & 511;
    float gi = bih[n]        + bhh[n];
    float gf = bih[n + 512]  + bhh[n + 512];
    float gg = bih[n + 1024] + bhh[n + 1024];
    float go = bih[n + 1536] + bhh[n + 1536];
#pragma unroll
    for (int zz = 0; zz < 8; zz++) {
        const float* gs = g_gs + zz * (B_ * 2048) + b * 2048;
        gi += gs[n]; gf += gs[n + 512]; gg += gs[n + 1024]; go += gs[n + 1536];
    }
    float c  = g_hc[b * 1024 + 512 + n];
    float i_ = 1.f / (1.f + expf(-gi));
    float f_ = 1.f / (1.f + expf(-gf));
    float o_ = 1.f / (1.f + expf(-go));
    float cn = f_ * c + i_ * tanhf(gg);
    float hn = o_ * tanhf(cn);
    g_hall[((size_t)b * TMX + t) * 512 + n] = hn;
    if (t < (lens[b] - 1)) {
        g_hc[b * 1024 + n] = hn;
        g_hc[b * 1024 + 512 + n] = cn;
    }
}

// =====================================================================
extern "C" void kernel_launch(void* const* d_in, const int* in_sizes, int n_in,
                              void* d_out, int out_size)
{
    const float* input     = (const float*)d_in[0];
    const int*   captions  = (const int*)  d_in[1];
    const int*   lens      = (const int*)  d_in[2];
    const float* embed_w   = (const float*)d_in[3];
    const float* enc_att_w = (const float*)d_in[4];
    const float* enc_att_b = (const float*)d_in[5];
    const float* dec_att_w = (const float*)d_in[6];
    const float* dec_att_b = (const float*)d_in[7];
    const float* att_w     = (const float*)d_in[8];
    const float* att_b     = (const float*)d_in[9];
    const float* h_w       = (const float*)d_in[10];
    const float* h_b       = (const float*)d_in[11];
    const float* c_w       = (const float*)d_in[12];
    const float* c_b       = (const float*)d_in[13];
    const float* actv_w    = (const float*)d_in[14];
    const float* actv_b    = (const float*)d_in[15];
    const float* wih       = (const float*)d_in[16];
    const float* whh       = (const float*)d_in[17];
    const float* bih       = (const float*)d_in[18];
    const float* bhh       = (const float*)d_in[19];
    const float* fc_w      = (const float*)d_in[20];
    const float* fc_b      = (const float*)d_in[21];

    float* out      = (float*)d_out;
    float* outProbs = out + (size_t)B_ * TMX * V_;

    void* p;
    cudaGetSymbolAddress(&p, g_mean);    float* p_mean    = (float*)p;
    cudaGetSymbolAddress(&p, g_hc);      float* p_hc      = (float*)p;
    cudaGetSymbolAddress(&p, g_hcslab);  float* p_hcslab  = (float*)p;
    cudaGetSymbolAddress(&p, g_encslab); float* p_encslab = (float*)p;
    cudaGetSymbolAddress(&p, g_emb);     float* p_emb     = (float*)p;
    cudaGetSymbolAddress(&p, g_hp);      float* p_hp      = (float*)p;
    cudaGetSymbolAddress(&p, g_gattv);   float* p_gattv   = (float*)p;
    cudaGetSymbolAddress(&p, g_gs);      float* p_gs      = (float*)p;
    cudaGetSymbolAddress(&p, g_hall);    float* p_hall    = (float*)p;

    const int HUGE_K = 1 << 30;

    mean_kernel<<<(B_ * ENC_ + 255) / 256, 256>>>(input);

    gemm_f32<4><<<dim3(8, 1, 16), 256>>>(
        p_mean, HUGE_K, ENC_,  p_mean, 0, 0,  p_mean, 0,
        h_w, c_w, HUGE_K, 512, 512, 512,
        64, 1024, 128, 0,
        p_hcslab, (long long)B_ * 1024, nullptr, 0, nullptr, nullptr);
    hc_reduce<<<(B_ * 1024) / 256, 256>>>(h_b, c_b);

    gemm_f32<8><<<dim3(4, 25, 2), 256>>>(
        input, HUGE_K, ENC_,  input, 0, 0,  input, 0,
        enc_att_w, enc_att_w, HUGE_K, HUGE_K, 512, 512,
        3136, 512, 1024, 0,
        p_encslab, (long long)3136 * 512, nullptr, 0, nullptr, nullptr);
    enc_reduce<<<(3136 * 512) / 256, 256>>>(enc_att_b);

    emb_gather<<<(TMX * B_ * 512 + 255) / 256, 256>>>(embed_w, captions);

    for (int t = 0; t < TMX; t++) {
        gemm_f32<4><<<dim3(20, 1, 4), 256>>>(
            p_hc, HUGE_K, 1024,  p_hc, 0, 0,  p_hc, 0,
            dec_att_w, actv_w, HUGE_K, 512, 512, 2048,
            64, 2560, 128, 0,
            p_hp, (long long)B_ * 2560, nullptr, 0, nullptr, nullptr);

        attn_kernel<<<B_, 256>>>(input, dec_att_b, att_w, att_b, actv_b,
                                 lens, outProbs, t);

        gemm_f32<4><<<dim3(16, 1, 8), 256>>>(
            p_emb + (size_t)t * B_ * 512, 512, 512,
            p_gattv, 2048, 2048,
            p_hc, 1024,
            wih, whh, 2560, HUGE_K, 2048, 2048,
            64, 2048, 384, 1,
            p_gs, (long long)B_ * 2048, nullptr, 0, nullptr, nullptr);

        lstm_kernel<<<(B_ * 512) / 256, 256>>>(bih, bhh, lens, t);
    }

    gemm_f32<8><<<dim3(79, 30, 1), 256>>>(
        p_hall, HUGE_K, 512,  p_hall, 0, 0,  p_hall, 0,
        fc_w, fc_w, HUGE_K, HUGE_K, V_, V_,
        3776, V_, 512, 0,
        nullptr, 0, fc_b, 2, lens, out);
}

// round 4
// speedup vs baseline: 1.5388x; 1.1902x over previous
#include <cuda_runtime.h>
#include <math.h>

typedef unsigned long long ull;

#define B_   64
#define L_   49
#define ENC_ 2048
#define TMX  59
#define V_   10000
#define BK   16
#define BM   64
#define BN   256
#define NBLK 128
#define HUGE_ 0x3FFFFFFF

// ---------------- scratch ----------------
__device__ float g_mean[B_ * ENC_];
__device__ float g_hc[B_ * 1024];
__device__ float g_hcslab[16 * B_ * 1024];
__device__ float g_encslab[4 * 3136 * 512];
__device__ float g_encproj[3136 * 512];
__device__ float g_emb[TMX * B_ * 512];
__device__ float g_hp[8 * B_ * 2560];
__device__ float g_gattv[B_ * 2048];
__device__ float g_gs[16 * B_ * 2048];
__device__ float g_hall[B_ * TMX * 512];     // row (b*59+t) x 512
__device__ int   g_rowmap[B_ * TMX];
__device__ int   g_nactive;
__device__ unsigned int g_bar_count;
__device__ unsigned int g_bar_gen;

// ---------------- f32x2 helpers ----------------
__device__ __forceinline__ ull pk2(float lo, float hi) {
    ull r; asm("mov.b64 %0, {%1,%2};" : "=l"(r) : "f"(lo), "f"(hi)); return r;
}
__device__ __forceinline__ void fma2(ull& d, ull a, ull b) {
    asm("fma.rn.f32x2 %0, %1, %2, %0;" : "+l"(d) : "l"(a), "l"(b));
}
__device__ __forceinline__ float2 upk2(ull v) {
    float2 f; asm("mov.b64 {%0,%1}, %2;" : "=f"(f.x), "=f"(f.y) : "l"(v)); return f;
}

// =====================================================================
// GEMM body. 512 threads. BM=64, BN=256, BK=16. Warp grid 2x8 (32x32
// warp tiles), lane grid 8x4 (4 rows x 8 cols per lane). Geometry is
// template-folded. smem: A duplicated f32x2 [2][16][64] (16KB) +
// W raw floats [2][16][256] (32KB) = 48KB.
// =====================================================================
template<int KA0, int LDA0, int KA1, int LDA1, int LDA2,
         int WSPLITK, int WSPLITN, int LDWA, int LDWB,
         int NTOT, int KSLAB, int GATHER, int EPI>
__device__ __forceinline__ void gemm_body(
    const float* __restrict__ A0, const float* __restrict__ A1,
    const float* __restrict__ A2, const int* __restrict__ rowIdx,
    const float* __restrict__ Wa, const float* __restrict__ Wb,
    int Mtot,
    float* __restrict__ Cslab, long long slabStride,
    const float* __restrict__ bias, float* __restrict__ outPred,
    int bx, int by, int z, char* smemRaw)
{
    ull*   As = (ull*)smemRaw;                   // [2][16][64]
    float* Ws = (float*)(smemRaw + 16384);       // [2][16][256]

    const int tid  = threadIdx.x;
    const int w    = tid >> 5, lane = tid & 31;
    const int wr   = w & 1,   wc   = w >> 1;
    const int lr   = lane >> 2, lc = lane & 3;
    const int row0 = by * BM;
    const int kbase = z * KSLAB;
    const int mlim = (EPI == 2) ? g_nactive : Mtot;

    float4 avreg = make_float4(0, 0, 0, 0);
    float4 wvreg[2];

    auto loadA = [&](int kb) {
        if (tid < 256) {
            int m  = tid >> 2;
            int k4 = (tid & 3) * 4;
            int k  = kb + k4;
            int mg = row0 + m;
            float4 v = make_float4(0.f, 0.f, 0.f, 0.f);
            if (mg < mlim) {
                int arow = rowIdx ? rowIdx[mg] : mg;
                const float* Ap; int kr, lda;
                if (k < KA0)            { Ap = A0; kr = k;             lda = LDA0; }
                else if (k < KA0 + KA1) { Ap = A1; kr = k - KA0;       lda = LDA1; }
                else                    { Ap = A2; kr = k - KA0 - KA1; lda = LDA2; }
                v = __ldcg((const float4*)&Ap[(size_t)arow * lda + kr]);
            }
            avreg = v;
        }
    };
    auto loadW = [&](int kb) {
#pragma unroll
        for (int p = 0; p < 2; p++) {
            int id = tid + p * 512;
            int k  = kb + (id >> 6);
            int j4 = (id & 63) * 4;
            int pc = GATHER ? ((j4 >> 6) * 512 + bx * 64 + (j4 & 63)) : (bx * BN + j4);
            const float* Wp = Wa; int kr = k, cc = pc, ldw = LDWA;
            if (k >= WSPLITK)       { Wp = Wb; kr = k - WSPLITK;  ldw = LDWB; }
            else if (pc >= WSPLITN) { Wp = Wb; cc = pc - WSPLITN; ldw = LDWB; }
            float4 v;
            if (pc + 3 < NTOT) {
                v = *(const float4*)&Wp[(size_t)kr * ldw + cc];
            } else {
                v.x = (pc     < NTOT) ? Wp[(size_t)kr * ldw + cc]     : 0.f;
                v.y = (pc + 1 < NTOT) ? Wp[(size_t)kr * ldw + cc + 1] : 0.f;
                v.z = (pc + 2 < NTOT) ? Wp[(size_t)kr * ldw + cc + 2] : 0.f;
                v.w = 0.f;
            }
            wvreg[p] = v;
        }
    };
    auto stage = [&](int buf) {
        if (tid < 256) {
            int m = tid >> 2, k4 = (tid & 3) * 4;
            ull* a = As + buf * (16 * 64) + k4 * 64 + m;
            a[0]   = pk2(avreg.x, avreg.x);
            a[64]  = pk2(avreg.y, avreg.y);
            a[128] = pk2(avreg.z, avreg.z);
            a[192] = pk2(avreg.w, avreg.w);
        }
#pragma unroll
        for (int p = 0; p < 2; p++) {
            int id = tid + p * 512;
            int k = id >> 6, j4 = (id & 63) * 4;
            *(float4*)&Ws[buf * 4096 + k * 256 + j4] = wvreg[p];
        }
    };

    ull acc[4][4];
#pragma unroll
    for (int r = 0; r < 4; r++)
#pragma unroll
        for (int c = 0; c < 4; c++) acc[r][c] = 0ull;

    constexpr int nCh = KSLAB / BK;
    loadA(kbase); loadW(kbase); stage(0);
    __syncthreads();

#pragma unroll 1
    for (int ch = 0; ch < nCh; ch++) {
        const int cb = ch & 1;
        const bool more = (ch + 1) < nCh;
        if (more) { loadA(kbase + (ch + 1) * BK); loadW(kbase + (ch + 1) * BK); }

        const ull*   Ab = As + cb * (16 * 64) + wr * 32 + lr * 4;
        const float* Wp = Ws + cb * 4096 + wc * 32 + lc * 8;
#pragma unroll
        for (int kk = 0; kk < BK; kk++) {
            ulonglong2 a01 = *(const ulonglong2*)(Ab + kk * 64);
            ulonglong2 a23 = *(const ulonglong2*)(Ab + kk * 64 + 2);
            ulonglong2 w01 = *(const ulonglong2*)(Wp + kk * 256);
            ulonglong2 w23 = *(const ulonglong2*)(Wp + kk * 256 + 4);
            fma2(acc[0][0], a01.x, w01.x); fma2(acc[0][1], a01.x, w01.y);
            fma2(acc[0][2], a01.x, w23.x); fma2(acc[0][3], a01.x, w23.y);
            fma2(acc[1][0], a01.y, w01.x); fma2(acc[1][1], a01.y, w01.y);
            fma2(acc[1][2], a01.y, w23.x); fma2(acc[1][3], a01.y, w23.y);
            fma2(acc[2][0], a23.x, w01.x); fma2(acc[2][1], a23.x, w01.y);
            fma2(acc[2][2], a23.x, w23.x); fma2(acc[2][3], a23.x, w23.y);
            fma2(acc[3][0], a23.y, w01.x); fma2(acc[3][1], a23.y, w01.y);
            fma2(acc[3][2], a23.y, w23.x); fma2(acc[3][3], a23.y, w23.y);
        }
        if (more) stage(cb ^ 1);
        __syncthreads();
    }

#pragma unroll
    for (int r = 0; r < 4; r++) {
        int ml = row0 + wr * 32 + lr * 4 + r;
        if (ml >= mlim) continue;
#pragma unroll
        for (int c = 0; c < 4; c++) {
            float2 f = upk2(acc[r][c]);
            int j  = wc * 32 + lc * 8 + 2 * c;
            int pc = GATHER ? ((j >> 6) * 512 + bx * 64 + (j & 63)) : (bx * BN + j);
            if (EPI == 2) {
                int orow = rowIdx[ml];
                size_t base = (size_t)orow * V_;
                if (pc + 1 < NTOT) {
                    float2 o; o.x = f.x + bias[pc]; o.y = f.y + bias[pc + 1];
                    *(float2*)&outPred[base + pc] = o;
                } else if (pc < NTOT) {
                    outPred[base + pc] = f.x + bias[pc];
                }
            } else {
                float* o = Cslab + (size_t)z * slabStride + (size_t)ml * NTOT;
                *(float2*)&o[pc] = f;
            }
        }
    }
}

// ---------------- standalone GEMM wrappers ----------------
__global__ void __launch_bounds__(512, 1) gemm_h0c0(
    const float* h_w, const float* c_w)
{
    __shared__ char smem[49152];
    gemm_body<HUGE_, 2048, 0, 1, 1, HUGE_, 512, 512, 512, 1024, 128, 0, 0>(
        g_mean, g_mean, g_mean, nullptr, h_w, c_w, 64,
        g_hcslab, (long long)B_ * 1024, nullptr, nullptr,
        blockIdx.x, blockIdx.y, blockIdx.z, smem);
}

__global__ void __launch_bounds__(512, 1) gemm_enc(
    const float* input, const float* enc_att_w)
{
    __shared__ char smem[49152];
    gemm_body<HUGE_, 2048, 0, 1, 1, HUGE_, HUGE_, 512, 512, 512, 512, 0, 0>(
        input, input, input, nullptr, enc_att_w, enc_att_w, 3136,
        g_encslab, (long long)3136 * 512, nullptr, nullptr,
        blockIdx.x, blockIdx.y, blockIdx.z, smem);
}

__global__ void __launch_bounds__(512, 1) gemm_fc(
    const float* fc_w, const float* fc_b, float* out)
{
    __shared__ char smem[49152];
    if ((int)(blockIdx.y * BM) >= g_nactive) return;
    gemm_body<HUGE_, 512, 0, 1, 1, HUGE_, HUGE_, V_, V_, V_, 512, 0, 2>(
        g_hall, g_hall, g_hall, g_rowmap, fc_w, fc_w, B_ * TMX,
        nullptr, 0, fc_b, out,
        blockIdx.x, blockIdx.y, 0, smem);
}

// ---------------- grid barrier ----------------
__device__ __forceinline__ void gbar() {
    __syncthreads();
    if (threadIdx.x == 0) {
        __threadfence();
        unsigned int gen = *(volatile unsigned int*)&g_bar_gen;
        unsigned int arrived = atomicAdd(&g_bar_count, 1u);
        if (arrived == NBLK - 1) {
            g_bar_count = 0;
            __threadfence();
            atomicAdd(&g_bar_gen, 1u);
        } else {
            while (*(volatile unsigned int*)&g_bar_gen == gen) { __nanosleep(100); }
        }
        __threadfence();
    }
    __syncthreads();
}

// ---------------- attention phase (one block per b, 512 threads) ----------------
__device__ void attn_body(int b, int t,
    const float* __restrict__ input,
    const float* __restrict__ dec_b,
    const float* __restrict__ att_w,
    const float* __restrict__ att_b,
    const float* __restrict__ actv_b,
    const int* __restrict__ lens,
    float* __restrict__ outProbs, char* smemRaw)
{
    float* sd = (float*)smemRaw;   // 512
    float* sp = sd + 512;          // 64
    const int tid = threadIdx.x;

    {
        float s = dec_b[tid];
#pragma unroll
        for (int zz = 0; zz < 8; zz++) s += __ldcg(&g_hp[zz * (B_ * 2560) + b * 2560 + tid]);
        sd[tid] = s;
    }
    __syncthreads();

    const int w = tid >> 5, lane = tid & 31;
    for (int l = w; l < L_; l += 16) {
        const float* ep = g_encproj + ((size_t)b * L_ + l) * 512;
        float s = 0.f;
#pragma unroll
        for (int a = lane; a < 512; a += 32) {
            float v = fmaxf(ep[a] + sd[a], 0.f);
            s = fmaf(v, att_w[a], s);
        }
#pragma unroll
        for (int o = 16; o; o >>= 1) s += __shfl_xor_sync(~0u, s, o);
        if (lane == 0) sp[l] = s + att_b[0];
    }
    __syncthreads();

    if (w == 0) {
        float v0 = (lane < L_) ? sp[lane] : -1e30f;
        float v1 = (lane + 32 < L_) ? sp[lane + 32] : -1e30f;
        float mx = fmaxf(v0, v1);
#pragma unroll
        for (int o = 16; o; o >>= 1) mx = fmaxf(mx, __shfl_xor_sync(~0u, mx, o));
        float e0 = (lane < L_) ? expf(v0 - mx) : 0.f;
        float e1 = (lane + 32 < L_) ? expf(v1 - mx) : 0.f;
        float sm = e0 + e1;
#pragma unroll
        for (int o = 16; o; o >>= 1) sm += __shfl_xor_sync(~0u, sm, o);
        float inv = 1.f / sm;
        if (lane < L_) sp[lane] = e0 * inv;
        if (lane + 32 < L_) sp[lane + 32] = e1 * inv;
    }
    __syncthreads();

    const bool act = t < (lens[b] - 1);
    if (tid < L_) outProbs[((size_t)b * TMX + t) * L_ + tid] = act ? sp[tid] : 0.f;

    const int e0i = tid * 4;
    float4 a0 = make_float4(0, 0, 0, 0);
    const float* ip = input + (size_t)b * L_ * ENC_ + e0i;
    for (int l = 0; l < L_; l++) {
        float p = sp[l];
        float4 x = *(const float4*)(ip + (size_t)l * ENC_);
        a0.x = fmaf(p, x.x, a0.x); a0.y = fmaf(p, x.y, a0.y);
        a0.z = fmaf(p, x.z, a0.z); a0.w = fmaf(p, x.w, a0.w);
    }
    float res[4] = {a0.x, a0.y, a0.z, a0.w};
#pragma unroll
    for (int i = 0; i < 4; i++) {
        int e = e0i + i;
        float hp = actv_b[e];
#pragma unroll
        for (int zz = 0; zz < 8; zz++) hp += __ldcg(&g_hp[zz * (B_ * 2560) + b * 2560 + 512 + e]);
        float gate = 1.f / (1.f + expf(-hp));
        g_gattv[b * ENC_ + e] = gate * res[i];
    }
}

// ---------------- lstm phase ----------------
__device__ void lstm_body(int blk, int t,
    const float* __restrict__ bih, const float* __restrict__ bhh,
    const int* __restrict__ lens)
{
    int idx = blk * 512 + threadIdx.x;        // 64*512
    int b = idx >> 9, n = idx & 511;
    float gi = bih[n]        + bhh[n];
    float gf = bih[n + 512]  + bhh[n + 512];
    float gg = bih[n + 1024] + bhh[n + 1024];
    float go = bih[n + 1536] + bhh[n + 1536];
#pragma unroll
    for (int zz = 0; zz < 16; zz++) {
        const float* gs = g_gs + zz * (B_ * 2048) + b * 2048;
        gi += __ldcg(&gs[n]);        gf += __ldcg(&gs[n + 512]);
        gg += __ldcg(&gs[n + 1024]); go += __ldcg(&gs[n + 1536]);
    }
    float c  = __ldcg(&g_hc[b * 1024 + 512 + n]);
    float i_ = 1.f / (1.f + expf(-gi));
    float f_ = 1.f / (1.f + expf(-gf));
    float o_ = 1.f / (1.f + expf(-go));
    float cn = f_ * c + i_ * tanhf(gg);
    float hn = o_ * tanhf(cn);
    g_hall[((size_t)b * TMX + t) * 512 + n] = hn;
    if (t < (lens[b] - 1)) {
        g_hc[b * 1024 + n] = hn;
        g_hc[b * 1024 + 512 + n] = cn;
    }
}

// ---------------- persistent recurrence kernel ----------------
__global__ void __launch_bounds__(512, 1) recur_kernel(
    const float* input, const int* lens,
    const float* dec_att_w, const float* dec_att_b,
    const float* att_w, const float* att_b,
    const float* actv_w, const float* actv_b,
    const float* wih, const float* whh,
    const float* bih, const float* bhh,
    float* outProbs)
{
    __shared__ char smem[49152];
    const int blk = blockIdx.x;

    for (int t = 0; t < TMX; t++) {
        // phase 1: hp = h @ [dec_att_w | actv_w]   (10 col-blocks x 8 splits)
        if (blk < 80) {
            gemm_body<HUGE_, 1024, 0, 1, 1, HUGE_, 512, 512, 2048, 2560, 64, 0, 0>(
                g_hc, g_hc, g_hc, nullptr, dec_att_w, actv_w, 64,
                g_hp, (long long)B_ * 2560, nullptr, nullptr,
                blk % 10, 0, blk / 10, smem);
        }
        gbar();

        // phase 2: attention + softmax + att_vec + gate
        if (blk < 64)
            attn_body(blk, t, input, dec_att_b, att_w, att_b, actv_b, lens, outProbs, smem);
        gbar();

        // phase 3: gates = [emb_t | gattv | h] @ [wih; whh]  (8 cols x 16 splits)
        gemm_body<512, 512, 2048, 2048, 1024, 2560, HUGE_, 2048, 2048, 2048, 192, 1, 0>(
            g_emb + (size_t)t * B_ * 512, g_gattv, g_hc, nullptr, wih, whh, 64,
            g_gs, (long long)B_ * 2048, nullptr, nullptr,
            blk & 7, 0, blk >> 3, smem);
        gbar();

        // phase 4: slab reduce + LSTM pointwise + carry update
        if (blk < 64) lstm_body(blk, t, bih, bhh, lens);
        gbar();
    }
}

// ---------------- small kernels ----------------
__global__ void mean_kernel(const float* __restrict__ in) {
    int idx = blockIdx.x * 256 + threadIdx.x;
    if (idx >= B_ * ENC_) return;
    int b = idx >> 11, e = idx & 2047;
    float s = 0.f;
#pragma unroll 7
    for (int l = 0; l < L_; l++) s += in[((size_t)b * L_ + l) * ENC_ + e];
    g_mean[idx] = s * (1.0f / 49.0f);
}

__global__ void hc_reduce(const float* __restrict__ hb, const float* __restrict__ cb) {
    int idx = blockIdx.x * 256 + threadIdx.x;
    int n = idx & 1023;
    float s = (n < 512) ? hb[n] : cb[n - 512];
#pragma unroll
    for (int zz = 0; zz < 16; zz++) s += g_hcslab[zz * (B_ * 1024) + idx];
    g_hc[idx] = s;
}

__global__ void enc_reduce(const float* __restrict__ eb) {
    int idx = blockIdx.x * 256 + threadIdx.x;
    float s = eb[idx & 511];
#pragma unroll
    for (int zz = 0; zz < 4; zz++) s += g_encslab[zz * (3136 * 512) + idx];
    g_encproj[idx] = s;
}

__global__ void emb_gather(const float* __restrict__ embed_w, const int* __restrict__ captions) {
    int idx = blockIdx.x * 256 + threadIdx.x;
    if (idx >= TMX * B_ * 512) return;
    int e = idx & 511;
    int tb = idx >> 9;
    int b = tb & 63, t = tb >> 6;
    int tok = captions[b * 60 + t];
    g_emb[idx] = embed_w[(size_t)tok * 512 + e];
}

__global__ void rowmap_kernel(const int* __restrict__ lens) {
    __shared__ int off[B_ + 1];
    int tid = threadIdx.x;    // 64 threads
    if (tid == 0) {
        int acc = 0;
        for (int b = 0; b < B_; b++) {
            off[b] = acc;
            int pl = lens[b] - 1;
            if (pl < 0) pl = 0; if (pl > TMX) pl = TMX;
            acc += pl;
        }
        off[B_] = acc;
        g_nactive = acc;
    }
    __syncthreads();
    int pl = lens[tid] - 1;
    if (pl < 0) pl = 0; if (pl > TMX) pl = TMX;
    int o = off[tid];
    for (int t = 0; t < pl; t++) g_rowmap[o + t] = tid * TMX + t;
}

__global__ void zerofill_kernel(const int* __restrict__ lens, float* __restrict__ out) {
    int row = blockIdx.x;     // 0..3775
    int b = row / TMX, t = row - b * TMX;
    if (t < lens[b] - 1) return;   // active row: fc writes it
    float4 z4 = make_float4(0.f, 0.f, 0.f, 0.f);
    float* o = out + (size_t)row * V_;
    for (int i = threadIdx.x * 4; i < V_; i += 512 * 4)
        *(float4*)&o[i] = z4;
}

// =====================================================================
extern "C" void kernel_launch(void* const* d_in, const int* in_sizes, int n_in,
                              void* d_out, int out_size)
{
    const float* input     = (const float*)d_in[0];
    const int*   captions  = (const int*)  d_in[1];
    const int*   lens      = (const int*)  d_in[2];
    const float* embed_w   = (const float*)d_in[3];
    const float* enc_att_w = (const float*)d_in[4];
    const float* enc_att_b = (const float*)d_in[5];
    const float* dec_att_w = (const float*)d_in[6];
    const float* dec_att_b = (const float*)d_in[7];
    const float* att_w     = (const float*)d_in[8];
    const float* att_b     = (const float*)d_in[9];
    const float* h_w       = (const float*)d_in[10];
    const float* h_b       = (const float*)d_in[11];
    const float* c_w       = (const float*)d_in[12];
    const float* c_b       = (const float*)d_in[13];
    const float* actv_w    = (const float*)d_in[14];
    const float* actv_b    = (const float*)d_in[15];
    const float* wih       = (const float*)d_in[16];
    const float* whh       = (const float*)d_in[17];
    const float* bih       = (const float*)d_in[18];
    const float* bhh       = (const float*)d_in[19];
    const float* fc_w      = (const float*)d_in[20];
    const float* fc_b      = (const float*)d_in[21];

    float* out      = (float*)d_out;
    float* outProbs = out + (size_t)B_ * TMX * V_;

    // 1) prep
    mean_kernel<<<(B_ * ENC_ + 255) / 256, 256>>>(input);
    gemm_h0c0<<<dim3(4, 1, 16), 512>>>(h_w, c_w);
    hc_reduce<<<(B_ * 1024) / 256, 256>>>(h_b, c_b);
    gemm_enc<<<dim3(2, 49, 4), 512>>>(input, enc_att_w);
    enc_reduce<<<(3136 * 512) / 256, 256>>>(enc_att_b);
    emb_gather<<<(TMX * B_ * 512 + 255) / 256, 256>>>(embed_w, captions);
    rowmap_kernel<<<1, 64>>>(lens);

    // 2) persistent recurrence (all 59 steps, grid barriers between phases)
    recur_kernel<<<NBLK, 512>>>(input, lens, dec_att_w, dec_att_b,
                                att_w, att_b, actv_w, actv_b,
                                wih, whh, bih, bhh, outProbs);

    // 3) deferred fc over packed active rows + zero-fill of inactive rows
    zerofill_kernel<<<B_ * TMX, 512>>>(lens, out);
    gemm_fc<<<dim3(40, 59, 1), 512>>>(fc_w, fc_b, out);
}

// round 5
// speedup vs baseline: 1.8685x; 1.2142x over previous
#include <cuda_runtime.h>
#include <math.h>

typedef unsigned long long ull;

#define B_   64
#define L_   49
#define ENC_ 2048
#define TMX  59
#define V_   10000
#define BK   16
#define BM   64
#define BN   128
#define NBLK 256
#define HUGE_ 0x3FFFFFFF

#define ASTRIDE 68
#define SM_A_BYTES (2 * 16 * ASTRIDE * 4)          // 8704
#define SM_TOTAL   (SM_A_BYTES + 2 * 16 * 128 * 4) // 25088

// ---------------- scratch ----------------
__device__ float g_mean[B_ * ENC_];
__device__ float g_hc[B_ * 1024];
__device__ float g_hcslab[16 * B_ * 1024];
__device__ float g_encslab[2 * 3136 * 512];
__device__ float g_encproj[3136 * 512];
__device__ float g_emb[TMX * B_ * 512];
__device__ float g_hp[8 * B_ * 2560];
__device__ float g_gattv[B_ * 2048];
__device__ float g_gs[16 * B_ * 2048];
__device__ float g_hall[B_ * TMX * 512];     // row (b*59+t) x 512
__device__ int   g_rowmap[B_ * TMX];
__device__ int   g_nactive;
__device__ unsigned int g_bar_count;
__device__ unsigned int g_bar_gen;

// ---------------- f32x2 helpers ----------------
__device__ __forceinline__ ull pk2(float lo, float hi) {
    ull r; asm("mov.b64 %0, {%1,%2};" : "=l"(r) : "f"(lo), "f"(hi)); return r;
}
__device__ __forceinline__ void fma2(ull& d, ull a, ull b) {
    asm("fma.rn.f32x2 %0, %1, %2, %0;" : "+l"(d) : "l"(a), "l"(b));
}
__device__ __forceinline__ float2 upk2(ull v) {
    float2 f; asm("mov.b64 {%0,%1}, %2;" : "=f"(f.x), "=f"(f.y) : "l"(v)); return f;
}

// =====================================================================
// GEMM body: 256 threads, BM=64, BN=128, BK=16, row-paired f32x2.
// Warp grid 2x4 (32x32 warp tiles); lane: lr=lane>>2 (4 rows = 2 pairs),
// lc=lane&3 (8 cols). A raw col-major in smem (LDS.128 = 2 row-pairs),
// W raw row-major; W duplicated per-use via mov.b64.
// =====================================================================
template<int KA0, int LDA0, int KA1, int LDA1, int LDA2,
         int WSPLITK, int WSPLITN, int LDWA, int LDWB,
         int NTOT, int KSLAB, int GATHER, int EPI>
__device__ __forceinline__ void gemm_body(
    const float* __restrict__ A0, const float* __restrict__ A1,
    const float* __restrict__ A2, const int* __restrict__ rowIdx,
    const float* __restrict__ Wa, const float* __restrict__ Wb,
    int Mtot,
    float* __restrict__ Cslab, long long slabStride,
    const float* __restrict__ bias, float* __restrict__ outPred,
    int bx, int by, int z, char* smemRaw)
{
    float* As = (float*)smemRaw;                    // [2][16][ASTRIDE]
    float* Ws = (float*)(smemRaw + SM_A_BYTES);     // [2][16][128]

    const int tid  = threadIdx.x;
    const int w    = tid >> 5, lane = tid & 31;
    const int wr   = w & 1,   wc   = w >> 1;        // 2 x 4
    const int lr   = lane >> 2, lc = lane & 3;
    const int row0 = by * BM;
    const int kbase = z * KSLAB;
    const int mlim = (EPI == 2) ? g_nactive : Mtot;

    float4 avreg = make_float4(0, 0, 0, 0);
    float4 wvreg[2];

    auto loadA = [&](int kb) {
        int m  = tid >> 2;
        int k4 = (tid & 3) * 4;
        int k  = kb + k4;
        int mg = row0 + m;
        float4 v = make_float4(0.f, 0.f, 0.f, 0.f);
        if (mg < mlim) {
            int arow = rowIdx ? rowIdx[mg] : mg;
            const float* Ap; int kr, lda;
            if (k < KA0)            { Ap = A0; kr = k;             lda = LDA0; }
            else if (k < KA0 + KA1) { Ap = A1; kr = k - KA0;       lda = LDA1; }
            else                    { Ap = A2; kr = k - KA0 - KA1; lda = LDA2; }
            v = __ldcg((const float4*)&Ap[(size_t)arow * lda + kr]);
        }
        avreg = v;
    };
    auto loadW = [&](int kb) {
#pragma unroll
        for (int p = 0; p < 2; p++) {
            int id = tid + p * 256;
            int k  = kb + (id >> 5);
            int j4 = (id & 31) * 4;
            int pc = GATHER ? ((j4 >> 5) * 512 + bx * 32 + (j4 & 31)) : (bx * BN + j4);
            const float* Wp = Wa; int kr = k, cc = pc, ldw = LDWA;
            if (k >= WSPLITK)       { Wp = Wb; kr = k - WSPLITK;  ldw = LDWB; }
            else if (pc >= WSPLITN) { Wp = Wb; cc = pc - WSPLITN; ldw = LDWB; }
            float4 v;
            if (pc + 3 < NTOT) {
                v = *(const float4*)&Wp[(size_t)kr * ldw + cc];
            } else {
                v.x = (pc     < NTOT) ? Wp[(size_t)kr * ldw + cc]     : 0.f;
                v.y = (pc + 1 < NTOT) ? Wp[(size_t)kr * ldw + cc + 1] : 0.f;
                v.z = (pc + 2 < NTOT) ? Wp[(size_t)kr * ldw + cc + 2] : 0.f;
                v.w = 0.f;
            }
            wvreg[p] = v;
        }
    };
    auto stage = [&](int buf) {
        {
            int m = tid >> 2, k4 = (tid & 3) * 4;
            float* a = As + (buf * 16 + k4) * ASTRIDE + m;
            a[0]           = avreg.x;
            a[ASTRIDE]     = avreg.y;
            a[2 * ASTRIDE] = avreg.z;
            a[3 * ASTRIDE] = avreg.w;
        }
#pragma unroll
        for (int p = 0; p < 2; p++) {
            int id = tid + p * 256;
            int k = id >> 5, j4 = (id & 31) * 4;
            *(float4*)&Ws[(buf * 16 + k) * 128 + j4] = wvreg[p];
        }
    };

    ull acc[2][8];
#pragma unroll
    for (int r = 0; r < 2; r++)
#pragma unroll
        for (int c = 0; c < 8; c++) acc[r][c] = 0ull;

    constexpr int nCh = KSLAB / BK;
    loadA(kbase); loadW(kbase); stage(0);
    __syncthreads();

#pragma unroll 1
    for (int ch = 0; ch < nCh; ch++) {
        const int cb = ch & 1;
        const bool more = (ch + 1) < nCh;
        if (more) { loadA(kbase + (ch + 1) * BK); loadW(kbase + (ch + 1) * BK); }

        const float* Ab = As + cb * (16 * ASTRIDE) + wr * 32 + lr * 4;
        const float* Wp = Ws + cb * (16 * 128) + wc * 32 + lc * 8;
#pragma unroll
        for (int kk = 0; kk < BK; kk++) {
            float4 a4 = *(const float4*)(Ab + kk * ASTRIDE);
            ull ap0 = *(ull*)&a4.x;
            ull ap1 = *(ull*)&a4.z;
            float4 w0 = *(const float4*)(Wp + kk * 128);
            float4 w1 = *(const float4*)(Wp + kk * 128 + 4);
            ull d0 = pk2(w0.x, w0.x), d1 = pk2(w0.y, w0.y);
            ull d2 = pk2(w0.z, w0.z), d3 = pk2(w0.w, w0.w);
            ull d4 = pk2(w1.x, w1.x), d5 = pk2(w1.y, w1.y);
            ull d6 = pk2(w1.z, w1.z), d7 = pk2(w1.w, w1.w);
            fma2(acc[0][0], ap0, d0); fma2(acc[0][1], ap0, d1);
            fma2(acc[0][2], ap0, d2); fma2(acc[0][3], ap0, d3);
            fma2(acc[0][4], ap0, d4); fma2(acc[0][5], ap0, d5);
            fma2(acc[0][6], ap0, d6); fma2(acc[0][7], ap0, d7);
            fma2(acc[1][0], ap1, d0); fma2(acc[1][1], ap1, d1);
            fma2(acc[1][2], ap1, d2); fma2(acc[1][3], ap1, d3);
            fma2(acc[1][4], ap1, d4); fma2(acc[1][5], ap1, d5);
            fma2(acc[1][6], ap1, d6); fma2(acc[1][7], ap1, d7);
        }
        if (more) stage(cb ^ 1);
        __syncthreads();
    }

    // ---- epilogue: rows r..r+3, 8 consecutive cols per lane ----
#pragma unroll
    for (int rr = 0; rr < 4; rr++) {
        int ml = row0 + wr * 32 + lr * 4 + rr;
        if (ml >= mlim) continue;
        float v[8];
#pragma unroll
        for (int c = 0; c < 8; c++) {
            float2 f = upk2(acc[rr >> 1][c]);
            v[c] = (rr & 1) ? f.y : f.x;
        }
        int j0 = wc * 32 + lc * 8;
        if (EPI == 2) {
            int orow = rowIdx[ml];
            size_t base = (size_t)orow * V_;
            int pc0 = bx * BN + j0;
            if (pc0 + 7 < NTOT) {
                float4 o0, o1;
                o0.x = v[0] + bias[pc0];     o0.y = v[1] + bias[pc0 + 1];
                o0.z = v[2] + bias[pc0 + 2]; o0.w = v[3] + bias[pc0 + 3];
                o1.x = v[4] + bias[pc0 + 4]; o1.y = v[5] + bias[pc0 + 5];
                o1.z = v[6] + bias[pc0 + 6]; o1.w = v[7] + bias[pc0 + 7];
                *(float4*)&outPred[base + pc0]     = o0;
                *(float4*)&outPred[base + pc0 + 4] = o1;
            } else {
#pragma unroll
                for (int c = 0; c < 8; c++) {
                    int pc = pc0 + c;
                    if (pc < NTOT) outPred[base + pc] = v[c] + bias[pc];
                }
            }
        } else {
            int pc0 = GATHER ? (wc * 512 + bx * 32 + lc * 8) : (bx * BN + j0);
            float* o = Cslab + (size_t)z * slabStride + (size_t)ml * NTOT + pc0;
            *(float4*)&o[0] = make_float4(v[0], v[1], v[2], v[3]);
            *(float4*)&o[4] = make_float4(v[4], v[5], v[6], v[7]);
        }
    }
}

// ---------------- standalone GEMM wrappers ----------------
__global__ void __launch_bounds__(256, 2) gemm_h0c0(
    const float* h_w, const float* c_w)
{
    __shared__ char smem[SM_TOTAL];
    gemm_body<HUGE_, 2048, 0, 1, 1, HUGE_, 512, 512, 512, 1024, 128, 0, 0>(
        g_mean, g_mean, g_mean, nullptr, h_w, c_w, 64,
        g_hcslab, (long long)B_ * 1024, nullptr, nullptr,
        blockIdx.x, 0, blockIdx.z, smem);
}

__global__ void __launch_bounds__(256, 2) gemm_enc(
    const float* input, const float* enc_att_w)
{
    __shared__ char smem[SM_TOTAL];
    gemm_body<HUGE_, 2048, 0, 1, 1, HUGE_, HUGE_, 512, 512, 512, 1024, 0, 0>(
        input, input, input, nullptr, enc_att_w, enc_att_w, 3136,
        g_encslab, (long long)3136 * 512, nullptr, nullptr,
        blockIdx.x, blockIdx.y, blockIdx.z, smem);
}

__global__ void __launch_bounds__(256, 2) gemm_fc(
    const float* fc_w, const float* fc_b, float* out)
{
    __shared__ char smem[SM_TOTAL];
    if ((int)(blockIdx.y * BM) >= g_nactive) return;
    gemm_body<HUGE_, 512, 0, 1, 1, HUGE_, HUGE_, V_, V_, V_, 512, 0, 2>(
        g_hall, g_hall, g_hall, g_rowmap, fc_w, fc_w, B_ * TMX,
        nullptr, 0, fc_b, out,
        blockIdx.x, blockIdx.y, 0, smem);
}

// ---------------- grid barrier ----------------
__device__ __forceinline__ void gbar() {
    __syncthreads();
    if (threadIdx.x == 0) {
        __threadfence();
        unsigned int gen = *(volatile unsigned int*)&g_bar_gen;
        unsigned int arrived = atomicAdd(&g_bar_count, 1u);
        if (arrived == NBLK - 1) {
            g_bar_count = 0;
            __threadfence();
            atomicAdd(&g_bar_gen, 1u);
        } else {
            while (*(volatile unsigned int*)&g_bar_gen == gen) {}
        }
        __threadfence();
    }
    __syncthreads();
}

// ---------------- attention phase (one block per b, 256 threads) ----------------
__device__ void attn_body(int b, int t,
    const float* __restrict__ input,
    const float* __restrict__ dec_b,
    const float* __restrict__ att_w,
    const float* __restrict__ att_b,
    const float* __restrict__ actv_b,
    const int* __restrict__ lens,
    float* __restrict__ outProbs, char* smemRaw)
{
    float* sd = (float*)smemRaw;   // 512
    float* sp = sd + 512;          // 64
    const int tid = threadIdx.x;

    for (int i = tid; i < 512; i += 256) {
        float s = dec_b[i];
#pragma unroll
        for (int zz = 0; zz < 8; zz++) s += __ldcg(&g_hp[zz * (B_ * 2560) + b * 2560 + i]);
        sd[i] = s;
    }
    __syncthreads();

    const int w = tid >> 5, lane = tid & 31;
    for (int l = w; l < L_; l += 8) {
        const float* ep = g_encproj + ((size_t)b * L_ + l) * 512;
        float s = 0.f;
#pragma unroll
        for (int a = lane; a < 512; a += 32) {
            float v = fmaxf(ep[a] + sd[a], 0.f);
            s = fmaf(v, att_w[a], s);
        }
#pragma unroll
        for (int o = 16; o; o >>= 1) s += __shfl_xor_sync(~0u, s, o);
        if (lane == 0) sp[l] = s + att_b[0];
    }
    __syncthreads();

    if (w == 0) {
        float v0 = (lane < L_) ? sp[lane] : -1e30f;
        float v1 = (lane + 32 < L_) ? sp[lane + 32] : -1e30f;
        float mx = fmaxf(v0, v1);
#pragma unroll
        for (int o = 16; o; o >>= 1) mx = fmaxf(mx, __shfl_xor_sync(~0u, mx, o));
        float e0 = (lane < L_) ? expf(v0 - mx) : 0.f;
        float e1 = (lane + 32 < L_) ? expf(v1 - mx) : 0.f;
        float sm = e0 + e1;
#pragma unroll
        for (int o = 16; o; o >>= 1) sm += __shfl_xor_sync(~0u, sm, o);
        float inv = 1.f / sm;
        if (lane < L_) sp[lane] = e0 * inv;
        if (lane + 32 < L_) sp[lane + 32] = e1 * inv;
    }
    __syncthreads();

    const bool act = t < (lens[b] - 1);
    if (tid < L_) outProbs[((size_t)b * TMX + t) * L_ + tid] = act ? sp[tid] : 0.f;

    const int e0i = tid * 8;
    float4 a0 = make_float4(0, 0, 0, 0), a1 = make_float4(0, 0, 0, 0);
    const float* ip = input + (size_t)b * L_ * ENC_ + e0i;
    for (int l = 0; l < L_; l++) {
        float p = sp[l];
        float4 x0 = *(const float4*)(ip + (size_t)l * ENC_);
        float4 x1 = *(const float4*)(ip + (size_t)l * ENC_ + 4);
        a0.x = fmaf(p, x0.x, a0.x); a0.y = fmaf(p, x0.y, a0.y);
        a0.z = fmaf(p, x0.z, a0.z); a0.w = fmaf(p, x0.w, a0.w);
        a1.x = fmaf(p, x1.x, a1.x); a1.y = fmaf(p, x1.y, a1.y);
        a1.z = fmaf(p, x1.z, a1.z); a1.w = fmaf(p, x1.w, a1.w);
    }
    float res[8] = {a0.x, a0.y, a0.z, a0.w, a1.x, a1.y, a1.z, a1.w};
#pragma unroll
    for (int i = 0; i < 8; i++) {
        int e = e0i + i;
        float hp = actv_b[e];
#pragma unroll
        for (int zz = 0; zz < 8; zz++) hp += __ldcg(&g_hp[zz * (B_ * 2560) + b * 2560 + 512 + e]);
        float gate = 1.f / (1.f + expf(-hp));
        g_gattv[b * ENC_ + e] = gate * res[i];
    }
}

// ---------------- lstm phase (128 blocks x 256 threads) ----------------
__device__ void lstm_body(int blk, int t,
    const float* __restrict__ bih, const float* __restrict__ bhh,
    const int* __restrict__ lens)
{
    int idx = blk * 256 + threadIdx.x;        // 64*512
    int b = idx >> 9, n = idx & 511;
    float gi = bih[n]        + bhh[n];
    float gf = bih[n + 512]  + bhh[n + 512];
    float gg = bih[n + 1024] + bhh[n + 1024];
    float go = bih[n + 1536] + bhh[n + 1536];
#pragma unroll
    for (int zz = 0; zz < 16; zz++) {
        const float* gs = g_gs + zz * (B_ * 2048) + b * 2048;
        gi += __ldcg(&gs[n]);        gf += __ldcg(&gs[n + 512]);
        gg += __ldcg(&gs[n + 1024]); go += __ldcg(&gs[n + 1536]);
    }
    float c  = __ldcg(&g_hc[b * 1024 + 512 + n]);
    float i_ = 1.f / (1.f + expf(-gi));
    float f_ = 1.f / (1.f + expf(-gf));
    float o_ = 1.f / (1.f + expf(-go));
    float cn = f_ * c + i_ * tanhf(gg);
    float hn = o_ * tanhf(cn);
    g_hall[((size_t)b * TMX + t) * 512 + n] = hn;
    if (t < (lens[b] - 1)) {
        g_hc[b * 1024 + n] = hn;
        g_hc[b * 1024 + 512 + n] = cn;
    }
}

// ---------------- persistent recurrence kernel (256 blocks x 256 thr) ----------------
__global__ void __launch_bounds__(256, 2) recur_kernel(
    const float* input, const int* lens,
    const float* dec_att_w, const float* dec_att_b,
    const float* att_w, const float* att_b,
    const float* actv_w, const float* actv_b,
    const float* wih, const float* whh,
    const float* bih, const float* bhh,
    float* outProbs)
{
    __shared__ char smem[SM_TOTAL];
    const int blk = blockIdx.x;

    for (int t = 0; t < TMX; t++) {
        // phase 1: hp = h @ [dec_att_w | actv_w]  (20 col-tiles x 8 splits = 160)
        if (blk < 160) {
            gemm_body<HUGE_, 1024, 0, 1, 1, HUGE_, 512, 512, 2048, 2560, 64, 0, 0>(
                g_hc, g_hc, g_hc, nullptr, dec_att_w, actv_w, 64,
                g_hp, (long long)B_ * 2560, nullptr, nullptr,
                blk % 20, 0, blk / 20, smem);
        }
        gbar();

        // phase 2: attention + softmax + att_vec + gate
        if (blk < 64)
            attn_body(blk, t, input, dec_att_b, att_w, att_b, actv_b, lens, outProbs, smem);
        gbar();

        // phase 3: gates = [emb_t | gattv | h] @ [wih; whh]  (16 cols x 16 splits = 256)
        gemm_body<512, 512, 2048, 2048, 1024, 2560, HUGE_, 2048, 2048, 2048, 192, 1, 0>(
            g_emb + (size_t)t * B_ * 512, g_gattv, g_hc, nullptr, wih, whh, 64,
            g_gs, (long long)B_ * 2048, nullptr, nullptr,
            blk & 15, 0, blk >> 4, smem);
        gbar();

        // phase 4: slab reduce + LSTM pointwise + carry update
        if (blk < 128) lstm_body(blk, t, bih, bhh, lens);
        gbar();
    }
}

// ---------------- small kernels ----------------
__global__ void mean_kernel(const float* __restrict__ in) {
    int idx = blockIdx.x * 256 + threadIdx.x;
    if (idx >= B_ * ENC_) return;
    int b = idx >> 11, e = idx & 2047;
    float s = 0.f;
#pragma unroll 7
    for (int l = 0; l < L_; l++) s += in[((size_t)b * L_ + l) * ENC_ + e];
    g_mean[idx] = s * (1.0f / 49.0f);
}

__global__ void hc_reduce(const float* __restrict__ hb, const float* __restrict__ cb) {
    int idx = blockIdx.x * 256 + threadIdx.x;
    int n = idx & 1023;
    float s = (n < 512) ? hb[n] : cb[n - 512];
#pragma unroll
    for (int zz = 0; zz < 16; zz++) s += g_hcslab[zz * (B_ * 1024) + idx];
    g_hc[idx] = s;
}

__global__ void enc_reduce(const float* __restrict__ eb) {
    int idx = blockIdx.x * 256 + threadIdx.x;
    g_encproj[idx] = g_encslab[idx] + g_encslab[3136 * 512 + idx] + eb[idx & 511];
}

__global__ void emb_gather(const float* __restrict__ embed_w, const int* __restrict__ captions) {
    int idx = blockIdx.x * 256 + threadIdx.x;
    if (idx >= TMX * B_ * 512) return;
    int e = idx & 511;
    int tb = idx >> 9;
    int b = tb & 63, t = tb >> 6;
    int tok = captions[b * 60 + t];
    g_emb[idx] = embed_w[(size_t)tok * 512 + e];
}

__global__ void rowmap_kernel(const int* __restrict__ lens) {
    __shared__ int off[B_ + 1];
    int tid = threadIdx.x;    // 64 threads
    if (tid == 0) {
        int acc = 0;
        for (int b = 0; b < B_; b++) {
            off[b] = acc;
            int pl = lens[b] - 1;
            if (pl < 0) pl = 0; if (pl > TMX) pl = TMX;
            acc += pl;
        }
        off[B_] = acc;
        g_nactive = acc;
    }
    __syncthreads();
    int pl = lens[tid] - 1;
    if (pl < 0) pl = 0; if (pl > TMX) pl = TMX;
    int o = off[tid];
    for (int t = 0; t < pl; t++) g_rowmap[o + t] = tid * TMX + t;
}

__global__ void zerofill_kernel(const int* __restrict__ lens, float* __restrict__ out) {
    int row = blockIdx.x;     // 0..3775
    int b = row / TMX, t = row - b * TMX;
    if (t < lens[b] - 1) return;   // active row: fc writes it
    float4 z4 = make_float4(0.f, 0.f, 0.f, 0.f);
    float* o = out + (size_t)row * V_;
    for (int i = threadIdx.x * 4; i < V_; i += 512 * 4)
        *(float4*)&o[i] = z4;
}

// =====================================================================
extern "C" void kernel_launch(void* const* d_in, const int* in_sizes, int n_in,
                              void* d_out, int out_size)
{
    const float* input     = (const float*)d_in[0];
    const int*   captions  = (const int*)  d_in[1];
    const int*   lens      = (const int*)  d_in[2];
    const float* embed_w   = (const float*)d_in[3];
    const float* enc_att_w = (const float*)d_in[4];
    const float* enc_att_b = (const float*)d_in[5];
    const float* dec_att_w = (const float*)d_in[6];
    const float* dec_att_b = (const float*)d_in[7];
    const float* att_w     = (const float*)d_in[8];
    const float* att_b     = (const float*)d_in[9];
    const float* h_w       = (const float*)d_in[10];
    const float* h_b       = (const float*)d_in[11];
    const float* c_w       = (const float*)d_in[12];
    const float* c_b       = (const float*)d_in[13];
    const float* actv_w    = (const float*)d_in[14];
    const float* actv_b    = (const float*)d_in[15];
    const float* wih       = (const float*)d_in[16];
    const float* whh       = (const float*)d_in[17];
    const float* bih       = (const float*)d_in[18];
    const float* bhh       = (const float*)d_in[19];
    const float* fc_w      = (const float*)d_in[20];
    const float* fc_b      = (const float*)d_in[21];

    float* out      = (float*)d_out;
    float* outProbs = out + (size_t)B_ * TMX * V_;

    // 1) prep
    mean_kernel<<<(B_ * ENC_ + 255) / 256, 256>>>(input);
    gemm_h0c0<<<dim3(8, 1, 16), 256>>>(h_w, c_w);
    hc_reduce<<<(B_ * 1024) / 256, 256>>>(h_b, c_b);
    gemm_enc<<<dim3(4, 49, 2), 256>>>(input, enc_att_w);
    enc_reduce<<<(3136 * 512) / 256, 256>>>(enc_att_b);
    emb_gather<<<(TMX * B_ * 512 + 255) / 256, 256>>>(embed_w, captions);
    rowmap_kernel<<<1, 64>>>(lens);

    // 2) persistent recurrence (all 59 steps, grid barriers between phases)
    recur_kernel<<<NBLK, 256>>>(input, lens, dec_att_w, dec_att_b,
                                att_w, att_b, actv_w, actv_b,
                                wih, whh, bih, bhh, outProbs);

    // 3) deferred fc over packed active rows + zero-fill of inactive rows
    zerofill_kernel<<<B_ * TMX, 512>>>(lens, out);
    gemm_fc<<<dim3(79, 59, 1), 256>>>(fc_w, fc_b, out);
}

// round 6
// speedup vs baseline: 2.0322x; 1.0876x over previous
#include <cuda_runtime.h>
#include <math.h>

typedef unsigned long long ull;

#define B_   64
#define L_   49
#define ENC_ 2048
#define TMX  59
#define V_   10000
#define BK   16
#define BM   64
#define BN   128
#define NBLK 256
#define HUGE_ 0x3FFFFFFF

#define ASTRIDE 68
#define SM_A_BYTES (2 * 16 * ASTRIDE * 4)          // 8704
#define SM_TOTAL   (SM_A_BYTES + 2 * 16 * 128 * 4) // 25088

// ---------------- scratch ----------------
__device__ float g_mean[B_ * ENC_];
__device__ float g_hc[B_ * 1024];
__device__ float g_hcslab[16 * B_ * 1024];
__device__ float g_encslab[2 * 3136 * 512];
__device__ float g_encproj[3136 * 512];
__device__ float g_emb[TMX * B_ * 512];
__device__ float g_hp[8 * B_ * 2560];
__device__ float g_gattv[B_ * 2048];
__device__ float g_gs[16 * B_ * 2048];
__device__ float g_hall[B_ * TMX * 512];     // row (b*59+t) x 512
__device__ int   g_rowmap[B_ * TMX];
__device__ int   g_nactive;
__device__ unsigned int g_bar_count;
__device__ unsigned int g_bar_gen;

// ---------------- f32x2 helpers ----------------
__device__ __forceinline__ ull pk2(float lo, float hi) {
    ull r; asm("mov.b64 %0, {%1,%2};" : "=l"(r) : "f"(lo), "f"(hi)); return r;
}
__device__ __forceinline__ void fma2(ull& d, ull a, ull b) {
    asm("fma.rn.f32x2 %0, %1, %2, %0;" : "+l"(d) : "l"(a), "l"(b));
}
__device__ __forceinline__ float2 upk2(ull v) {
    float2 f; asm("mov.b64 {%0,%1}, %2;" : "=f"(f.x), "=f"(f.y) : "l"(v)); return f;
}

// =====================================================================
// GEMM body: 256 threads, BM=64, BN=128, BK=16.
// Warp grid: 8 warps along N (warp tile 64x16).
// Lane grid: lr=lane>>2 (8 row groups x 8 rows), lc=lane&3 (4 col groups x 4).
// A raw col-major in smem: 2 LDS.128 per kk give 4 natural f32x2 row-pairs.
// W row-major; 1 LDS.128 gives 4 scalars, duplicated via 4 movs.
// 16 FFMA2 per kk per lane; acc[rowpair][col] = 16 ull.
// =====================================================================
template<int KA0, int LDA0, int KA1, int LDA1, int LDA2,
         int WSPLITK, int WSPLITN, int LDWA, int LDWB,
         int NTOT, int KSLAB, int GATHER, int EPI>
__device__ __forceinline__ void gemm_body(
    const float* __restrict__ A0, const float* __restrict__ A1,
    const float* __restrict__ A2, const int* __restrict__ rowIdx,
    const float* __restrict__ Wa, const float* __restrict__ Wb,
    int Mtot,
    float* __restrict__ Cslab, long long slabStride,
    const float* __restrict__ bias, float* __restrict__ outPred,
    int bx, int by, int z, char* smemRaw)
{
    float* As = (float*)smemRaw;                    // [2][16][ASTRIDE]
    float* Ws = (float*)(smemRaw + SM_A_BYTES);     // [2][16][128]

    const int tid  = threadIdx.x;
    const int w    = tid >> 5, lane = tid & 31;
    const int lr   = lane >> 2, lc = lane & 3;
    const int row0 = by * BM;
    const int kbase = z * KSLAB;
    const int mlim = (EPI == 2) ? g_nactive : Mtot;

    float4 avreg = make_float4(0, 0, 0, 0);
    float4 wvreg[2];

    auto loadA = [&](int kb) {
        int m  = tid >> 2;
        int k4 = (tid & 3) * 4;
        int k  = kb + k4;
        int mg = row0 + m;
        float4 v = make_float4(0.f, 0.f, 0.f, 0.f);
        if (mg < mlim) {
            int arow = rowIdx ? rowIdx[mg] : mg;
            const float* Ap; int kr, lda;
            if (k < KA0)            { Ap = A0; kr = k;             lda = LDA0; }
            else if (k < KA0 + KA1) { Ap = A1; kr = k - KA0;       lda = LDA1; }
            else                    { Ap = A2; kr = k - KA0 - KA1; lda = LDA2; }
            v = __ldcg((const float4*)&Ap[(size_t)arow * lda + kr]);
        }
        avreg = v;
    };
    auto loadW = [&](int kb) {
#pragma unroll
        for (int p = 0; p < 2; p++) {
            int id = tid + p * 256;
            int k  = kb + (id >> 5);
            int j4 = (id & 31) * 4;
            int pc = GATHER ? ((j4 >> 5) * 512 + bx * 32 + (j4 & 31)) : (bx * BN + j4);
            const float* Wp = Wa; int kr = k, cc = pc, ldw = LDWA;
            if (k >= WSPLITK)       { Wp = Wb; kr = k - WSPLITK;  ldw = LDWB; }
            else if (pc >= WSPLITN) { Wp = Wb; cc = pc - WSPLITN; ldw = LDWB; }
            float4 v;
            if (pc + 3 < NTOT) {
                v = *(const float4*)&Wp[(size_t)kr * ldw + cc];
            } else {
                v.x = (pc     < NTOT) ? Wp[(size_t)kr * ldw + cc]     : 0.f;
                v.y = (pc + 1 < NTOT) ? Wp[(size_t)kr * ldw + cc + 1] : 0.f;
                v.z = (pc + 2 < NTOT) ? Wp[(size_t)kr * ldw + cc + 2] : 0.f;
                v.w = 0.f;
            }
            wvreg[p] = v;
        }
    };
    auto stage = [&](int buf) {
        {
            int m = tid >> 2, k4 = (tid & 3) * 4;
            float* a = As + (buf * 16 + k4) * ASTRIDE + m;
            a[0]           = avreg.x;
            a[ASTRIDE]     = avreg.y;
            a[2 * ASTRIDE] = avreg.z;
            a[3 * ASTRIDE] = avreg.w;
        }
#pragma unroll
        for (int p = 0; p < 2; p++) {
            int id = tid + p * 256;
            int k = id >> 5, j4 = (id & 31) * 4;
            *(float4*)&Ws[(buf * 16 + k) * 128 + j4] = wvreg[p];
        }
    };

    ull acc[4][4];   // [row-pair][col]
#pragma unroll
    for (int r = 0; r < 4; r++)
#pragma unroll
        for (int c = 0; c < 4; c++) acc[r][c] = 0ull;

    constexpr int nCh = KSLAB / BK;
    loadA(kbase); loadW(kbase); stage(0);
    __syncthreads();

#pragma unroll 1
    for (int ch = 0; ch < nCh; ch++) {
        const int cb = ch & 1;
        const bool more = (ch + 1) < nCh;
        if (more) { loadA(kbase + (ch + 1) * BK); loadW(kbase + (ch + 1) * BK); }

        const float* Ab = As + cb * (16 * ASTRIDE) + lr * 8;
        const float* Wp = Ws + cb * (16 * 128) + w * 16 + lc * 4;
#pragma unroll
        for (int kk = 0; kk < BK; kk++) {
            float4 a0 = *(const float4*)(Ab + kk * ASTRIDE);
            float4 a1 = *(const float4*)(Ab + kk * ASTRIDE + 4);
            float4 w4 = *(const float4*)(Wp + kk * 128);
            ull p0 = *(ull*)&a0.x, p1 = *(ull*)&a0.z;
            ull p2 = *(ull*)&a1.x, p3 = *(ull*)&a1.z;
            ull d0 = pk2(w4.x, w4.x), d1 = pk2(w4.y, w4.y);
            ull d2 = pk2(w4.z, w4.z), d3 = pk2(w4.w, w4.w);
            fma2(acc[0][0], p0, d0); fma2(acc[0][1], p0, d1);
            fma2(acc[0][2], p0, d2); fma2(acc[0][3], p0, d3);
            fma2(acc[1][0], p1, d0); fma2(acc[1][1], p1, d1);
            fma2(acc[1][2], p1, d2); fma2(acc[1][3], p1, d3);
            fma2(acc[2][0], p2, d0); fma2(acc[2][1], p2, d1);
            fma2(acc[2][2], p2, d2); fma2(acc[2][3], p2, d3);
            fma2(acc[3][0], p3, d0); fma2(acc[3][1], p3, d1);
            fma2(acc[3][2], p3, d2); fma2(acc[3][3], p3, d3);
        }
        if (more) stage(cb ^ 1);
        __syncthreads();
    }

    // ---- epilogue: lane covers rows lr*8..lr*8+7, cols w*16+lc*4..+3 ----
    const int j0 = w * 16 + lc * 4;
#pragma unroll
    for (int rp = 0; rp < 4; rp++) {
#pragma unroll
        for (int half = 0; half < 2; half++) {
            int ml = row0 + lr * 8 + rp * 2 + half;
            if (ml >= mlim) continue;
            float v[4];
#pragma unroll
            for (int c = 0; c < 4; c++) {
                float2 f = upk2(acc[rp][c]);
                v[c] = half ? f.y : f.x;
            }
            if (EPI == 2) {
                int orow = rowIdx[ml];
                size_t base = (size_t)orow * V_;
                int pc0 = bx * BN + j0;
                if (pc0 + 3 < NTOT) {
                    float4 o;
                    o.x = v[0] + bias[pc0];     o.y = v[1] + bias[pc0 + 1];
                    o.z = v[2] + bias[pc0 + 2]; o.w = v[3] + bias[pc0 + 3];
                    *(float4*)&outPred[base + pc0] = o;
                } else {
#pragma unroll
                    for (int c = 0; c < 4; c++) {
                        int pc = pc0 + c;
                        if (pc < NTOT) outPred[base + pc] = v[c] + bias[pc];
                    }
                }
            } else {
                int pc0 = GATHER ? ((j0 >> 5) * 512 + bx * 32 + (j0 & 31)) : (bx * BN + j0);
                float* o = Cslab + (size_t)z * slabStride + (size_t)ml * NTOT + pc0;
                *(float4*)&o[0] = make_float4(v[0], v[1], v[2], v[3]);
            }
        }
    }
}

// ---------------- standalone GEMM wrappers ----------------
__global__ void __launch_bounds__(256, 2) gemm_h0c0(
    const float* h_w, const float* c_w)
{
    __shared__ char smem[SM_TOTAL];
    gemm_body<HUGE_, 2048, 0, 1, 1, HUGE_, 512, 512, 512, 1024, 128, 0, 0>(
        g_mean, g_mean, g_mean, nullptr, h_w, c_w, 64,
        g_hcslab, (long long)B_ * 1024, nullptr, nullptr,
        blockIdx.x, 0, blockIdx.z, smem);
}

__global__ void __launch_bounds__(256, 2) gemm_enc(
    const float* input, const float* enc_att_w)
{
    __shared__ char smem[SM_TOTAL];
    gemm_body<HUGE_, 2048, 0, 1, 1, HUGE_, HUGE_, 512, 512, 512, 1024, 0, 0>(
        input, input, input, nullptr, enc_att_w, enc_att_w, 3136,
        g_encslab, (long long)3136 * 512, nullptr, nullptr,
        blockIdx.x, blockIdx.y, blockIdx.z, smem);
}

__global__ void __launch_bounds__(256, 2) gemm_fc(
    const float* fc_w, const float* fc_b, float* out)
{
    __shared__ char smem[SM_TOTAL];
    if ((int)(blockIdx.y * BM) >= g_nactive) return;
    gemm_body<HUGE_, 512, 0, 1, 1, HUGE_, HUGE_, V_, V_, V_, 512, 0, 2>(
        g_hall, g_hall, g_hall, g_rowmap, fc_w, fc_w, B_ * TMX,
        nullptr, 0, fc_b, out,
        blockIdx.x, blockIdx.y, 0, smem);
}

// ---------------- grid barrier ----------------
__device__ __forceinline__ void gbar() {
    __syncthreads();
    if (threadIdx.x == 0) {
        __threadfence();
        unsigned int gen = *(volatile unsigned int*)&g_bar_gen;
        unsigned int arrived = atomicAdd(&g_bar_count, 1u);
        if (arrived == NBLK - 1) {
            g_bar_count = 0;
            __threadfence();
            atomicAdd(&g_bar_gen, 1u);
        } else {
            while (*(volatile unsigned int*)&g_bar_gen == gen) {}
        }
        __threadfence();
    }
    __syncthreads();
}

// ---------------- attention phase (one block per b, 256 threads) ----------------
__device__ void attn_body(int b, int t,
    const float* __restrict__ input,
    const float* __restrict__ dec_b,
    const float* __restrict__ att_w,
    const float* __restrict__ att_b,
    const float* __restrict__ actv_b,
    const int* __restrict__ lens,
    float* __restrict__ outProbs, char* smemRaw)
{
    float* sd = (float*)smemRaw;   // 512
    float* sp = sd + 512;          // 64
    const int tid = threadIdx.x;

    for (int i = tid; i < 512; i += 256) {
        float s = dec_b[i];
#pragma unroll
        for (int zz = 0; zz < 8; zz++) s += __ldcg(&g_hp[zz * (B_ * 2560) + b * 2560 + i]);
        sd[i] = s;
    }
    __syncthreads();

    const int w = tid >> 5, lane = tid & 31;
    for (int l = w; l < L_; l += 8) {
        const float* ep = g_encproj + ((size_t)b * L_ + l) * 512;
        float s = 0.f;
#pragma unroll
        for (int a = lane; a < 512; a += 32) {
            float v = fmaxf(ep[a] + sd[a], 0.f);
            s = fmaf(v, att_w[a], s);
        }
#pragma unroll
        for (int o = 16; o; o >>= 1) s += __shfl_xor_sync(~0u, s, o);
        if (lane == 0) sp[l] = s + att_b[0];
    }
    __syncthreads();

    if (w == 0) {
        float v0 = (lane < L_) ? sp[lane] : -1e30f;
        float v1 = (lane + 32 < L_) ? sp[lane + 32] : -1e30f;
        float mx = fmaxf(v0, v1);
#pragma unroll
        for (int o = 16; o; o >>= 1) mx = fmaxf(mx, __shfl_xor_sync(~0u, mx, o));
        float e0 = (lane < L_) ? expf(v0 - mx) : 0.f;
        float e1 = (lane + 32 < L_) ? expf(v1 - mx) : 0.f;
        float sm = e0 + e1;
#pragma unroll
        for (int o = 16; o; o >>= 1) sm += __shfl_xor_sync(~0u, sm, o);
        float inv = 1.f / sm;
        if (lane < L_) sp[lane] = e0 * inv;
        if (lane + 32 < L_) sp[lane + 32] = e1 * inv;
    }
    __syncthreads();

    const bool act = t < (lens[b] - 1);
    if (tid < L_) outProbs[((size_t)b * TMX + t) * L_ + tid] = act ? sp[tid] : 0.f;

    const int e0i = tid * 8;
    float4 a0 = make_float4(0, 0, 0, 0), a1 = make_float4(0, 0, 0, 0);
    const float* ip = input + (size_t)b * L_ * ENC_ + e0i;
    for (int l = 0; l < L_; l++) {
        float p = sp[l];
        float4 x0 = *(const float4*)(ip + (size_t)l * ENC_);
        float4 x1 = *(const float4*)(ip + (size_t)l * ENC_ + 4);
        a0.x = fmaf(p, x0.x, a0.x); a0.y = fmaf(p, x0.y, a0.y);
        a0.z = fmaf(p, x0.z, a0.z); a0.w = fmaf(p, x0.w, a0.w);
        a1.x = fmaf(p, x1.x, a1.x); a1.y = fmaf(p, x1.y, a1.y);
        a1.z = fmaf(p, x1.z, a1.z); a1.w = fmaf(p, x1.w, a1.w);
    }
    float res[8] = {a0.x, a0.y, a0.z, a0.w, a1.x, a1.y, a1.z, a1.w};
#pragma unroll
    for (int i = 0; i < 8; i++) {
        int e = e0i + i;
        float hp = actv_b[e];
#pragma unroll
        for (int zz = 0; zz < 8; zz++) hp += __ldcg(&g_hp[zz * (B_ * 2560) + b * 2560 + 512 + e]);
        float gate = 1.f / (1.f + expf(-hp));
        g_gattv[b * ENC_ + e] = gate * res[i];
    }
}

// ---------------- lstm phase (128 blocks x 256 threads) ----------------
__device__ void lstm_body(int blk, int t,
    const float* __restrict__ bih, const float* __restrict__ bhh,
    const int* __restrict__ lens)
{
    int idx = blk * 256 + threadIdx.x;        // 64*512
    int b = idx >> 9, n = idx & 511;
    float gi = bih[n]        + bhh[n];
    float gf = bih[n + 512]  + bhh[n + 512];
    float gg = bih[n + 1024] + bhh[n + 1024];
    float go = bih[n + 1536] + bhh[n + 1536];
#pragma unroll
    for (int zz = 0; zz < 16; zz++) {
        const float* gs = g_gs + zz * (B_ * 2048) + b * 2048;
        gi += __ldcg(&gs[n]);        gf += __ldcg(&gs[n + 512]);
        gg += __ldcg(&gs[n + 1024]); go += __ldcg(&gs[n + 1536]);
    }
    float c  = __ldcg(&g_hc[b * 1024 + 512 + n]);
    float i_ = 1.f / (1.f + expf(-gi));
    float f_ = 1.f / (1.f + expf(-gf));
    float o_ = 1.f / (1.f + expf(-go));
    float cn = f_ * c + i_ * tanhf(gg);
    float hn = o_ * tanhf(cn);
    g_hall[((size_t)b * TMX + t) * 512 + n] = hn;
    if (t < (lens[b] - 1)) {
        g_hc[b * 1024 + n] = hn;
        g_hc[b * 1024 + 512 + n] = cn;
    }
}

// ---------------- persistent recurrence kernel (256 blocks x 256 thr) ----------------
__global__ void __launch_bounds__(256, 2) recur_kernel(
    const float* input, const int* lens,
    const float* dec_att_w, const float* dec_att_b,
    const float* att_w, const float* att_b,
    const float* actv_w, const float* actv_b,
    const float* wih, const float* whh,
    const float* bih, const float* bhh,
    float* outProbs)
{
    __shared__ char smem[SM_TOTAL];
    const int blk = blockIdx.x;

    for (int t = 0; t < TMX; t++) {
        // phase 1: hp = h @ [dec_att_w | actv_w]  (20 col-tiles x 8 splits = 160)
        if (blk < 160) {
            gemm_body<HUGE_, 1024, 0, 1, 1, HUGE_, 512, 512, 2048, 2560, 64, 0, 0>(
                g_hc, g_hc, g_hc, nullptr, dec_att_w, actv_w, 64,
                g_hp, (long long)B_ * 2560, nullptr, nullptr,
                blk % 20, 0, blk / 20, smem);
        }
        gbar();

        // phase 2: attention + softmax + att_vec + gate
        if (blk < 64)
            attn_body(blk, t, input, dec_att_b, att_w, att_b, actv_b, lens, outProbs, smem);
        gbar();

        // phase 3: gates = [emb_t | gattv | h] @ [wih; whh]  (16 cols x 16 splits = 256)
        gemm_body<512, 512, 2048, 2048, 1024, 2560, HUGE_, 2048, 2048, 2048, 192, 1, 0>(
            g_emb + (size_t)t * B_ * 512, g_gattv, g_hc, nullptr, wih, whh, 64,
            g_gs, (long long)B_ * 2048, nullptr, nullptr,
            blk & 15, 0, blk >> 4, smem);
        gbar();

        // phase 4: slab reduce + LSTM pointwise + carry update
        if (blk < 128) lstm_body(blk, t, bih, bhh, lens);
        gbar();
    }
}

// ---------------- small kernels ----------------
__global__ void mean_kernel(const float* __restrict__ in) {
    int idx = blockIdx.x * 256 + threadIdx.x;
    if (idx >= B_ * ENC_) return;
    int b = idx >> 11, e = idx & 2047;
    float s = 0.f;
#pragma unroll 7
    for (int l = 0; l < L_; l++) s += in[((size_t)b * L_ + l) * ENC_ + e];
    g_mean[idx] = s * (1.0f / 49.0f);
}

__global__ void hc_reduce(const float* __restrict__ hb, const float* __restrict__ cb) {
    int idx = blockIdx.x * 256 + threadIdx.x;
    int n = idx & 1023;
    float s = (n < 512) ? hb[n] : cb[n - 512];
#pragma unroll
    for (int zz = 0; zz < 16; zz++) s += g_hcslab[zz * (B_ * 1024) + idx];
    g_hc[idx] = s;
}

__global__ void enc_reduce(const float* __restrict__ eb) {
    int idx = blockIdx.x * 256 + threadIdx.x;
    g_encproj[idx] = g_encslab[idx] + g_encslab[3136 * 512 + idx] + eb[idx & 511];
}

__global__ void emb_gather(const float* __restrict__ embed_w, const int* __restrict__ captions) {
    int idx = blockIdx.x * 256 + threadIdx.x;
    if (idx >= TMX * B_ * 512) return;
    int e = idx & 511;
    int tb = idx >> 9;
    int b = tb & 63, t = tb >> 6;
    int tok = captions[b * 60 + t];
    g_emb[idx] = embed_w[(size_t)tok * 512 + e];
}

__global__ void rowmap_kernel(const int* __restrict__ lens) {
    __shared__ int off[B_ + 1];
    int tid = threadIdx.x;    // 64 threads
    if (tid == 0) {
        int acc = 0;
        for (int b = 0; b < B_; b++) {
            off[b] = acc;
            int pl = lens[b] - 1;
            if (pl < 0) pl = 0; if (pl > TMX) pl = TMX;
            acc += pl;
        }
        off[B_] = acc;
        g_nactive = acc;
    }
    __syncthreads();
    int pl = lens[tid] - 1;
    if (pl < 0) pl = 0; if (pl > TMX) pl = TMX;
    int o = off[tid];
    for (int t = 0; t < pl; t++) g_rowmap[o + t] = tid * TMX + t;
}

__global__ void zerofill_kernel(const int* __restrict__ lens, float* __restrict__ out) {
    int row = blockIdx.x;     // 0..3775
    int b = row / TMX, t = row - b * TMX;
    if (t < lens[b] - 1) return;   // active row: fc writes it
    float4 z4 = make_float4(0.f, 0.f, 0.f, 0.f);
    float* o = out + (size_t)row * V_;
    for (int i = threadIdx.x * 4; i < V_; i += 512 * 4)
        *(float4*)&o[i] = z4;
}

// =====================================================================
extern "C" void kernel_launch(void* const* d_in, const int* in_sizes, int n_in,
                              void* d_out, int out_size)
{
    const float* input     = (const float*)d_in[0];
    const int*   captions  = (const int*)  d_in[1];
    const int*   lens      = (const int*)  d_in[2];
    const float* embed_w   = (const float*)d_in[3];
    const float* enc_att_w = (const float*)d_in[4];
    const float* enc_att_b = (const float*)d_in[5];
    const float* dec_att_w = (const float*)d_in[6];
    const float* dec_att_b = (const float*)d_in[7];
    const float* att_w     = (const float*)d_in[8];
    const float* att_b     = (const float*)d_in[9];
    const float* h_w       = (const float*)d_in[10];
    const float* h_b       = (const float*)d_in[11];
    const float* c_w       = (const float*)d_in[12];
    const float* c_b       = (const float*)d_in[13];
    const float* actv_w    = (const float*)d_in[14];
    const float* actv_b    = (const float*)d_in[15];
    const float* wih       = (const float*)d_in[16];
    const float* whh       = (const float*)d_in[17];
    const float* bih       = (const float*)d_in[18];
    const float* bhh       = (const float*)d_in[19];
    const float* fc_w      = (const float*)d_in[20];
    const float* fc_b      = (const float*)d_in[21];

    float* out      = (float*)d_out;
    float* outProbs = out + (size_t)B_ * TMX * V_;

    // 1) prep
    mean_kernel<<<(B_ * ENC_ + 255) / 256, 256>>>(input);
    gemm_h0c0<<<dim3(8, 1, 16), 256>>>(h_w, c_w);
    hc_reduce<<<(B_ * 1024) / 256, 256>>>(h_b, c_b);
    gemm_enc<<<dim3(4, 49, 2), 256>>>(input, enc_att_w);
    enc_reduce<<<(3136 * 512) / 256, 256>>>(enc_att_b);
    emb_gather<<<(TMX * B_ * 512 + 255) / 256, 256>>>(embed_w, captions);
    rowmap_kernel<<<1, 64>>>(lens);

    // 2) persistent recurrence (all 59 steps, grid barriers between phases)
    recur_kernel<<<NBLK, 256>>>(input, lens, dec_att_w, dec_att_b,
                                att_w, att_b, actv_w, actv_b,
                                wih, whh, bih, bhh, outProbs);

    // 3) deferred fc over packed active rows + zero-fill of inactive rows
    zerofill_kernel<<<B_ * TMX, 512>>>(lens, out);
    gemm_fc<<<dim3(79, 59, 1), 256>>>(fc_w, fc_b, out);
}

// round 8
// speedup vs baseline: 2.1154x; 1.0410x over previous
#include <cuda_runtime.h>
#include <math.h>

typedef unsigned long long ull;

#define B_   64
#define L_   49
#define ENC_ 2048
#define TMX  59
#define V_   10000
#define BK   16
#define BM   64
#define BN   128
#define NBLK 256
#define HUGE_ 0x3FFFFFFF

#define ASTRIDE 68
#define SM_A_BYTES (2 * 16 * ASTRIDE * 4)          // 8704
#define SM_TOTAL   (SM_A_BYTES + 2 * 16 * 128 * 4) // 25088

// ---------------- scratch ----------------
__device__ float g_mean[B_ * ENC_];
__device__ float g_hc[B_ * 1024];
__device__ float g_hcslab[16 * B_ * 1024];
__device__ float g_encslab[2 * 3136 * 512];
__device__ float g_encproj[3136 * 512];
__device__ float g_emb[TMX * B_ * 512];
__device__ float g_hp[8 * B_ * 2560];
__device__ float g_gattv[B_ * 2048];
__device__ float g_gs[16 * B_ * 2048];
__device__ float g_hall[B_ * TMX * 512];     // row (b*59+t) x 512
__device__ int   g_rowmap[B_ * TMX];
__device__ int   g_nactive;
__device__ unsigned int g_bar_count;
__device__ unsigned int g_bar_gen;

// ---------------- f32x2 helpers ----------------
__device__ __forceinline__ ull pk2(float lo, float hi) {
    ull r; asm("mov.b64 %0, {%1,%2};" : "=l"(r) : "f"(lo), "f"(hi)); return r;
}
__device__ __forceinline__ void fma2(ull& d, ull a, ull b) {
    asm("fma.rn.f32x2 %0, %1, %2, %0;" : "+l"(d) : "l"(a), "l"(b));
}
__device__ __forceinline__ float2 upk2(ull v) {
    float2 f; asm("mov.b64 {%0,%1}, %2;" : "=f"(f.x), "=f"(f.y) : "l"(v)); return f;
}

// =====================================================================
// GEMM body: 256 threads, BM=64, BN=128, BK=16.
// Warp grid: 8 warps along N (warp tile 64x16).
// Lane grid: lr=lane>>2 (8 row groups x 8 rows), lc=lane&3 (4 col groups x 4).
// A raw col-major in smem: 2 LDS.128 per kk give 4 natural f32x2 row-pairs.
// W row-major; 1 LDS.128 gives 4 scalars, duplicated via 4 movs.
// 2-chunk-ahead register pipeline (frags f0/f1, manual unroll-by-2;
// requires nCh even) over the double-buffered smem.
// =====================================================================
template<int KA0, int LDA0, int KA1, int LDA1, int LDA2,
         int WSPLITK, int WSPLITN, int LDWA, int LDWB,
         int NTOT, int KSLAB, int GATHER, int EPI>
__device__ __forceinline__ void gemm_body(
    const float* __restrict__ A0, const float* __restrict__ A1,
    const float* __restrict__ A2, const int* __restrict__ rowIdx,
    const float* __restrict__ Wa, const float* __restrict__ Wb,
    int Mtot,
    float* __restrict__ Cslab, long long slabStride,
    const float* __restrict__ bias, float* __restrict__ outPred,
    int bx, int by, int z, char* smemRaw)
{
    float* As = (float*)smemRaw;                    // [2][16][ASTRIDE]
    float* Ws = (float*)(smemRaw + SM_A_BYTES);     // [2][16][128]

    const int tid  = threadIdx.x;
    const int w    = tid >> 5, lane = tid & 31;
    const int lr   = lane >> 2, lc = lane & 3;
    const int row0 = by * BM;
    const int kbase = z * KSLAB;
    const int mlim = (EPI == 2) ? g_nactive : Mtot;

    // two register fragments (even/odd chunks)
    float4 avf0, avf1;
    float4 wvf0[2], wvf1[2];

    // fc whole-tile early exit
    if (EPI == 2) {
        if ((by * BM) >= mlim) return;
    }

    auto loadAv = [&](int kb) -> float4 {
        int m  = tid >> 2;
        int k4 = (tid & 3) * 4;
        int k  = kb + k4;
        int mg = row0 + m;
        float4 v = make_float4(0.f, 0.f, 0.f, 0.f);
        if (mg < mlim) {
            int arow = rowIdx ? rowIdx[mg] : mg;
            const float* Ap; int kr, lda;
            if (k < KA0)            { Ap = A0; kr = k;             lda = LDA0; }
            else if (k < KA0 + KA1) { Ap = A1; kr = k - KA0;       lda = LDA1; }
            else                    { Ap = A2; kr = k - KA0 - KA1; lda = LDA2; }
            v = __ldcg((const float4*)&Ap[(size_t)arow * lda + kr]);
        }
        return v;
    };
    auto loadWv = [&](int kb, float4* wv) {
#pragma unroll
        for (int p = 0; p < 2; p++) {
            int id = tid + p * 256;
            int k  = kb + (id >> 5);
            int j4 = (id & 31) * 4;
            int pc = GATHER ? ((j4 >> 5) * 512 + bx * 32 + (j4 & 31)) : (bx * BN + j4);
            const float* Wp = Wa; int kr = k, cc = pc, ldw = LDWA;
            if (k >= WSPLITK)       { Wp = Wb; kr = k - WSPLITK;  ldw = LDWB; }
            else if (pc >= WSPLITN) { Wp = Wb; cc = pc - WSPLITN; ldw = LDWB; }
            float4 v;
            if (pc + 3 < NTOT) {
                v = *(const float4*)&Wp[(size_t)kr * ldw + cc];
            } else {
                v.x = (pc     < NTOT) ? Wp[(size_t)kr * ldw + cc]     : 0.f;
                v.y = (pc + 1 < NTOT) ? Wp[(size_t)kr * ldw + cc + 1] : 0.f;
                v.z = (pc + 2 < NTOT) ? Wp[(size_t)kr * ldw + cc + 2] : 0.f;
                v.w = 0.f;
            }
            wv[p] = v;
        }
    };

    ull acc[4][4];
#pragma unroll
    for (int r = 0; r < 4; r++)
#pragma unroll
        for (int c = 0; c < 4; c++) acc[r][c] = 0ull;

    constexpr int nCh = KSLAB / BK;
    static_assert(nCh % 2 == 0, "nCh must be even for 2-deep pipeline");

    // ---- staging/compute as macros to keep reg indices static ----
#define STAGE_FRAG(BUF, AV, WV)                                        \
    do {                                                               \
        int m_ = tid >> 2, k4_ = (tid & 3) * 4;                        \
        float* a_ = As + ((BUF) * 16 + k4_) * ASTRIDE + m_;            \
        a_[0]           = (AV).x;                                      \
        a_[ASTRIDE]     = (AV).y;                                      \
        a_[2 * ASTRIDE] = (AV).z;                                      \
        a_[3 * ASTRIDE] = (AV).w;                                      \
        {                                                              \
            int id_ = tid;                                             \
            int k_ = id_ >> 5, j4_ = (id_ & 31) * 4;                   \
            *(float4*)&Ws[((BUF) * 16 + k_) * 128 + j4_] = (WV)[0];    \
        }                                                              \
        {                                                              \
            int id_ = tid + 256;                                       \
            int k_ = id_ >> 5, j4_ = (id_ & 31) * 4;                   \
            *(float4*)&Ws[((BUF) * 16 + k_) * 128 + j4_] = (WV)[1];    \
        }                                                              \
    } while (0)

#define COMPUTE_CHUNK(BUF)                                             \
    do {                                                               \
        const float* Ab = As + (BUF) * (16 * ASTRIDE) + lr * 8;        \
        const float* Wp = Ws + (BUF) * (16 * 128) + w * 16 + lc * 4;   \
        _Pragma("unroll")                                              \
        for (int kk = 0; kk < BK; kk++) {                              \
            float4 a0 = *(const float4*)(Ab + kk * ASTRIDE);           \
            float4 a1 = *(const float4*)(Ab + kk * ASTRIDE + 4);       \
            float4 w4 = *(const float4*)(Wp + kk * 128);               \
            ull p0 = *(ull*)&a0.x, p1 = *(ull*)&a0.z;                  \
            ull p2 = *(ull*)&a1.x, p3 = *(ull*)&a1.z;                  \
            ull d0 = pk2(w4.x, w4.x), d1 = pk2(w4.y, w4.y);            \
            ull d2 = pk2(w4.z, w4.z), d3 = pk2(w4.w, w4.w);            \
            fma2(acc[0][0], p0, d0); fma2(acc[0][1], p0, d1);          \
            fma2(acc[0][2], p0, d2); fma2(acc[0][3], p0, d3);          \
            fma2(acc[1][0], p1, d0); fma2(acc[1][1], p1, d1);          \
            fma2(acc[1][2], p1, d2); fma2(acc[1][3], p1, d3);          \
            fma2(acc[2][0], p2, d0); fma2(acc[2][1], p2, d1);          \
            fma2(acc[2][2], p2, d2); fma2(acc[2][3], p2, d3);          \
            fma2(acc[3][0], p3, d0); fma2(acc[3][1], p3, d1);          \
            fma2(acc[3][2], p3, d2); fma2(acc[3][3], p3, d3);          \
        }                                                              \
    } while (0)

    // prologue: load chunks 0 and 1, stage chunk 0
    avf0 = loadAv(kbase);            loadWv(kbase, wvf0);
    if (nCh > 1) { avf1 = loadAv(kbase + BK); loadWv(kbase + BK, wvf1); }
    STAGE_FRAG(0, avf0, wvf0);
    __syncthreads();

#pragma unroll 1
    for (int ch = 0; ch < nCh; ch += 2) {
        // even chunk: buf0 / frag0
        if (ch + 2 < nCh) { avf0 = loadAv(kbase + (ch + 2) * BK); loadWv(kbase + (ch + 2) * BK, wvf0); }
        COMPUTE_CHUNK(0);
        if (ch + 1 < nCh) STAGE_FRAG(1, avf1, wvf1);
        __syncthreads();

        // odd chunk: buf1 / frag1
        if (ch + 3 < nCh) { avf1 = loadAv(kbase + (ch + 3) * BK); loadWv(kbase + (ch + 3) * BK, wvf1); }
        COMPUTE_CHUNK(1);
        if (ch + 2 < nCh) STAGE_FRAG(0, avf0, wvf0);
        __syncthreads();
    }
#undef STAGE_FRAG
#undef COMPUTE_CHUNK

    // ---- epilogue: lane covers rows lr*8..lr*8+7, cols w*16+lc*4..+3 ----
    const int j0 = w * 16 + lc * 4;
#pragma unroll
    for (int rp = 0; rp < 4; rp++) {
#pragma unroll
        for (int half = 0; half < 2; half++) {
            int ml = row0 + lr * 8 + rp * 2 + half;
            if (ml >= mlim) continue;
            float v[4];
#pragma unroll
            for (int c = 0; c < 4; c++) {
                float2 f = upk2(acc[rp][c]);
                v[c] = half ? f.y : f.x;
            }
            if (EPI == 2) {
                int orow = rowIdx[ml];
                size_t base = (size_t)orow * V_;
                int pc0 = bx * BN + j0;
                if (pc0 + 3 < NTOT) {
                    float4 o;
                    o.x = v[0] + bias[pc0];     o.y = v[1] + bias[pc0 + 1];
                    o.z = v[2] + bias[pc0 + 2]; o.w = v[3] + bias[pc0 + 3];
                    *(float4*)&outPred[base + pc0] = o;
                } else {
#pragma unroll
                    for (int c = 0; c < 4; c++) {
                        int pc = pc0 + c;
                        if (pc < NTOT) outPred[base + pc] = v[c] + bias[pc];
                    }
                }
            } else {
                int pc0 = GATHER ? ((j0 >> 5) * 512 + bx * 32 + (j0 & 31)) : (bx * BN + j0);
                float* o = Cslab + (size_t)z * slabStride + (size_t)ml * NTOT + pc0;
                *(float4*)&o[0] = make_float4(v[0], v[1], v[2], v[3]);
            }
        }
    }
}

// ---------------- standalone GEMM wrappers ----------------
__global__ void __launch_bounds__(256, 2) gemm_h0c0(
    const float* h_w, const float* c_w)
{
    __shared__ char smem[SM_TOTAL];
    gemm_body<HUGE_, 2048, 0, 1, 1, HUGE_, 512, 512, 512, 1024, 128, 0, 0>(
        g_mean, g_mean, g_mean, nullptr, h_w, c_w, 64,
        g_hcslab, (long long)B_ * 1024, nullptr, nullptr,
        blockIdx.x, 0, blockIdx.z, smem);
}

__global__ void __launch_bounds__(256, 2) gemm_enc(
    const float* input, const float* enc_att_w)
{
    __shared__ char smem[SM_TOTAL];
    gemm_body<HUGE_, 2048, 0, 1, 1, HUGE_, HUGE_, 512, 512, 512, 1024, 0, 0>(
        input, input, input, nullptr, enc_att_w, enc_att_w, 3136,
        g_encslab, (long long)3136 * 512, nullptr, nullptr,
        blockIdx.x, blockIdx.y, blockIdx.z, smem);
}

__global__ void __launch_bounds__(256, 2) gemm_fc(
    const float* fc_w, const float* fc_b, float* out)
{
    __shared__ char smem[SM_TOTAL];
    gemm_body<HUGE_, 512, 0, 1, 1, HUGE_, HUGE_, V_, V_, V_, 512, 0, 2>(
        g_hall, g_hall, g_hall, g_rowmap, fc_w, fc_w, B_ * TMX,
        nullptr, 0, fc_b, out,
        blockIdx.x, blockIdx.y, 0, smem);
}

// ---------------- grid barrier ----------------
__device__ __forceinline__ void gbar() {
    __syncthreads();
    if (threadIdx.x == 0) {
        __threadfence();
        unsigned int gen = *(volatile unsigned int*)&g_bar_gen;
        unsigned int arrived = atomicAdd(&g_bar_count, 1u);
        if (arrived == NBLK - 1) {
            g_bar_count = 0;
            __threadfence();
            atomicAdd(&g_bar_gen, 1u);
        } else {
            while (*(volatile unsigned int*)&g_bar_gen == gen) {}
        }
        __threadfence();
    }
    __syncthreads();
}

// ---------------- attention phase (one block per b, 256 threads) ----------------
__device__ void attn_body(int b, int t,
    const float* __restrict__ input,
    const float* __restrict__ dec_b,
    const float* __restrict__ att_w,
    const float* __restrict__ att_b,
    const float* __restrict__ actv_b,
    const int* __restrict__ lens,
    float* __restrict__ outProbs, char* smemRaw)
{
    float* sd = (float*)smemRaw;   // 512
    float* sp = sd + 512;          // 64
    const int tid = threadIdx.x;

    for (int i = tid; i < 512; i += 256) {
        float s = dec_b[i];
#pragma unroll
        for (int zz = 0; zz < 8; zz++) s += __ldcg(&g_hp[zz * (B_ * 2560) + b * 2560 + i]);
        sd[i] = s;
    }
    __syncthreads();

    const int w = tid >> 5, lane = tid & 31;
    for (int l = w; l < L_; l += 8) {
        const float* ep = g_encproj + ((size_t)b * L_ + l) * 512;
        float s = 0.f;
#pragma unroll
        for (int a = lane; a < 512; a += 32) {
            float v = fmaxf(ep[a] + sd[a], 0.f);
            s = fmaf(v, att_w[a], s);
        }
#pragma unroll
        for (int o = 16; o; o >>= 1) s += __shfl_xor_sync(~0u, s, o);
        if (lane == 0) sp[l] = s + att_b[0];
    }
    __syncthreads();

    if (w == 0) {
        float v0 = (lane < L_) ? sp[lane] : -1e30f;
        float v1 = (lane + 32 < L_) ? sp[lane + 32] : -1e30f;
        float mx = fmaxf(v0, v1);
#pragma unroll
        for (int o = 16; o; o >>= 1) mx = fmaxf(mx, __shfl_xor_sync(~0u, mx, o));
        float e0 = (lane < L_) ? expf(v0 - mx) : 0.f;
        float e1 = (lane + 32 < L_) ? expf(v1 - mx) : 0.f;
        float sm = e0 + e1;
#pragma unroll
        for (int o = 16; o; o >>= 1) sm += __shfl_xor_sync(~0u, sm, o);
        float inv = 1.f / sm;
        if (lane < L_) sp[lane] = e0 * inv;
        if (lane + 32 < L_) sp[lane + 32] = e1 * inv;
    }
    __syncthreads();

    const bool act = t < (lens[b] - 1);
    if (tid < L_) outProbs[((size_t)b * TMX + t) * L_ + tid] = act ? sp[tid] : 0.f;

    const int e0i = tid * 8;
    float4 a0 = make_float4(0, 0, 0, 0), a1 = make_float4(0, 0, 0, 0);
    const float* ip = input + (size_t)b * L_ * ENC_ + e0i;
    for (int l = 0; l < L_; l++) {
        float p = sp[l];
        float4 x0 = *(const float4*)(ip + (size_t)l * ENC_);
        float4 x1 = *(const float4*)(ip + (size_t)l * ENC_ + 4);
        a0.x = fmaf(p, x0.x, a0.x); a0.y = fmaf(p, x0.y, a0.y);
        a0.z = fmaf(p, x0.z, a0.z); a0.w = fmaf(p, x0.w, a0.w);
        a1.x = fmaf(p, x1.x, a1.x); a1.y = fmaf(p, x1.y, a1.y);
        a1.z = fmaf(p, x1.z, a1.z); a1.w = fmaf(p, x1.w, a1.w);
    }
    float res[8] = {a0.x, a0.y, a0.z, a0.w, a1.x, a1.y, a1.z, a1.w};
#pragma unroll
    for (int i = 0; i < 8; i++) {
        int e = e0i + i;
        float hp = actv_b[e];
#pragma unroll
        for (int zz = 0; zz < 8; zz++) hp += __ldcg(&g_hp[zz * (B_ * 2560) + b * 2560 + 512 + e]);
        float gate = 1.f / (1.f + expf(-hp));
        g_gattv[b * ENC_ + e] = gate * res[i];
    }
}

// ---------------- lstm phase (128 blocks x 256 threads) ----------------
__device__ void lstm_body(int blk, int t,
    const float* __restrict__ bih, const float* __restrict__ bhh,
    const int* __restrict__ lens)
{
    int idx = blk * 256 + threadIdx.x;        // 64*512
    int b = idx >> 9, n = idx & 511;
    float gi = bih[n]        + bhh[n];
    float gf = bih[n + 512]  + bhh[n + 512];
    float gg = bih[n + 1024] + bhh[n + 1024];
    float go = bih[n + 1536] + bhh[n + 1536];
#pragma unroll
    for (int zz = 0; zz < 16; zz++) {
        const float* gs = g_gs + zz * (B_ * 2048) + b * 2048;
        gi += __ldcg(&gs[n]);        gf += __ldcg(&gs[n + 512]);
        gg += __ldcg(&gs[n + 1024]); go += __ldcg(&gs[n + 1536]);
    }
    float c  = __ldcg(&g_hc[b * 1024 + 512 + n]);
    float i_ = 1.f / (1.f + expf(-gi));
    float f_ = 1.f / (1.f + expf(-gf));
    float o_ = 1.f / (1.f + expf(-go));
    float cn = f_ * c + i_ * tanhf(gg);
    float hn = o_ * tanhf(cn);
    g_hall[((size_t)b * TMX + t) * 512 + n] = hn;
    if (t < (lens[b] - 1)) {
        g_hc[b * 1024 + n] = hn;
        g_hc[b * 1024 + 512 + n] = cn;
    }
}

// ---------------- persistent recurrence kernel (256 blocks x 256 thr) ----------------
__global__ void __launch_bounds__(256, 2) recur_kernel(
    const float* input, const int* lens,
    const float* dec_att_w, const float* dec_att_b,
    const float* att_w, const float* att_b,
    const float* actv_w, const float* actv_b,
    const float* wih, const float* whh,
    const float* bih, const float* bhh,
    float* outProbs)
{
    __shared__ char smem[SM_TOTAL];
    const int blk = blockIdx.x;

    for (int t = 0; t < TMX; t++) {
        // phase 1: hp = h @ [dec_att_w | actv_w]  (20 col-tiles x 8 splits = 160)
        if (blk < 160) {
            gemm_body<HUGE_, 1024, 0, 1, 1, HUGE_, 512, 512, 2048, 2560, 64, 0, 0>(
                g_hc, g_hc, g_hc, nullptr, dec_att_w, actv_w, 64,
                g_hp, (long long)B_ * 2560, nullptr, nullptr,
                blk % 20, 0, blk / 20, smem);
        }
        gbar();

        // phase 2: attention + softmax + att_vec + gate
        if (blk < 64)
            attn_body(blk, t, input, dec_att_b, att_w, att_b, actv_b, lens, outProbs, smem);
        gbar();

        // phase 3: gates = [emb_t | gattv | h] @ [wih; whh]  (16 cols x 16 splits = 256)
        gemm_body<512, 512, 2048, 2048, 1024, 2560, HUGE_, 2048, 2048, 2048, 192, 1, 0>(
            g_emb + (size_t)t * B_ * 512, g_gattv, g_hc, nullptr, wih, whh, 64,
            g_gs, (long long)B_ * 2048, nullptr, nullptr,
            blk & 15, 0, blk >> 4, smem);
        gbar();

        // phase 4: slab reduce + LSTM pointwise + carry update
        if (blk < 128) lstm_body(blk, t, bih, bhh, lens);
        gbar();
    }
}

// ---------------- small kernels ----------------
__global__ void mean_kernel(const float* __restrict__ in) {
    int idx = blockIdx.x * 256 + threadIdx.x;
    if (idx >= B_ * ENC_) return;
    int b = idx >> 11, e = idx & 2047;
    float s = 0.f;
#pragma unroll 7
    for (int l = 0; l < L_; l++) s += in[((size_t)b * L_ + l) * ENC_ + e];
    g_mean[idx] = s * (1.0f / 49.0f);
}

__global__ void hc_reduce(const float* __restrict__ hb, const float* __restrict__ cb) {
    int idx = blockIdx.x * 256 + threadIdx.x;
    int n = idx & 1023;
    float s = (n < 512) ? hb[n] : cb[n - 512];
#pragma unroll
    for (int zz = 0; zz < 16; zz++) s += g_hcslab[zz * (B_ * 1024) + idx];
    g_hc[idx] = s;
}

__global__ void enc_reduce(const float* __restrict__ eb) {
    int idx = blockIdx.x * 256 + threadIdx.x;
    g_encproj[idx] = g_encslab[idx] + g_encslab[3136 * 512 + idx] + eb[idx & 511];
}

__global__ void emb_gather(const float* __restrict__ embed_w, const int* __restrict__ captions) {
    int idx = blockIdx.x * 256 + threadIdx.x;
    if (idx >= TMX * B_ * 512) return;
    int e = idx & 511;
    int tb = idx >> 9;
    int b = tb & 63, t = tb >> 6;
    int tok = captions[b * 60 + t];
    g_emb[idx] = embed_w[(size_t)tok * 512 + e];
}

__global__ void rowmap_kernel(const int* __restrict__ lens) {
    __shared__ int off[B_ + 1];
    int tid = threadIdx.x;    // 64 threads
    if (tid == 0) {
        int acc = 0;
        for (int b = 0; b < B_; b++) {
            off[b] = acc;
            int pl = lens[b] - 1;
            if (pl < 0) pl = 0; if (pl > TMX) pl = TMX;
            acc += pl;
        }
        off[B_] = acc;
        g_nactive = acc;
    }
    __syncthreads();
    int pl = lens[tid] - 1;
    if (pl < 0) pl = 0; if (pl > TMX) pl = TMX;
    int o = off[tid];
    for (int t = 0; t < pl; t++) g_rowmap[o + t] = tid * TMX + t;
}

__global__ void zerofill_kernel(const int* __restrict__ lens, float* __restrict__ out) {
    int row = blockIdx.x;     // 0..3775
    int b = row / TMX, t = row - b * TMX;
    if (t < lens[b] - 1) return;   // active row: fc writes it
    float4 z4 = make_float4(0.f, 0.f, 0.f, 0.f);
    float* o = out + (size_t)row * V_;
    for (int i = threadIdx.x * 4; i < V_; i += 512 * 4)
        *(float4*)&o[i] = z4;
}

// =====================================================================
extern "C" void kernel_launch(void* const* d_in, const int* in_sizes, int n_in,
                              void* d_out, int out_size)
{
    const float* input     = (const float*)d_in[0];
    const int*   captions  = (const int*)  d_in[1];
    const int*   lens      = (const int*)  d_in[2];
    const float* embed_w   = (const float*)d_in[3];
    const float* enc_att_w = (const float*)d_in[4];
    const float* enc_att_b = (const float*)d_in[5];
    const float* dec_att_w = (const float*)d_in[6];
    const float* dec_att_b = (const float*)d_in[7];
    const float* att_w     = (const float*)d_in[8];
    const float* att_b     = (const float*)d_in[9];
    const float* h_w       = (const float*)d_in[10];
    const float* h_b       = (const float*)d_in[11];
    const float* c_w       = (const float*)d_in[12];
    const float* c_b       = (const float*)d_in[13];
    const float* actv_w    = (const float*)d_in[14];
    const float* actv_b    = (const float*)d_in[15];
    const float* wih       = (const float*)d_in[16];
    const float* whh       = (const float*)d_in[17];
    const float* bih       = (const float*)d_in[18];
    const float* bhh       = (const float*)d_in[19];
    const float* fc_w      = (const float*)d_in[20];
    const float* fc_b      = (const float*)d_in[21];

    float* out      = (float*)d_out;
    float* outProbs = out + (size_t)B_ * TMX * V_;

    // 1) prep
    mean_kernel<<<(B_ * ENC_ + 255) / 256, 256>>>(input);
    gemm_h0c0<<<dim3(8, 1, 16), 256>>>(h_w, c_w);
    hc_reduce<<<(B_ * 1024) / 256, 256>>>(h_b, c_b);
    gemm_enc<<<dim3(4, 49, 2), 256>>>(input, enc_att_w);
    enc_reduce<<<(3136 * 512) / 256, 256>>>(enc_att_b);
    emb_gather<<<(TMX * B_ * 512 + 255) / 256, 256>>>(embed_w, captions);
    rowmap_kernel<<<1, 64>>>(lens);

    // 2) persistent recurrence (all 59 steps, grid barriers between phases)
    recur_kernel<<<NBLK, 256>>>(input, lens, dec_att_w, dec_att_b,
                                att_w, att_b, actv_w, actv_b,
                                wih, whh, bih, bhh, outProbs);

    // 3) deferred fc over packed active rows + zero-fill of inactive rows
    zerofill_kernel<<<B_ * TMX, 512>>>(lens, out);
    gemm_fc<<<dim3(79, 59, 1), 256>>>(fc_w, fc_b, out);
}